// round 1
// baseline (speedup 1.0000x reference)
#include <cuda_runtime.h>

#define Bn   64
#define Cn   122
#define Tn   500
#define COn  64
#define Dn   128
#define Hn   8
#define FFn  256
#define Lln  2
#define BC   (Bn*Cn)        /* 7808 = 244*32 */
#define EPSf 1e-5f

/* ---------------- scratch (device globals; no allocation) ---------------- */
__device__ float g_tok[BC*Dn];
__device__ float g_qkv[BC*3*Dn];
__device__ float g_ctx[BC*Dn];
__device__ float g_ff [BC*FFn];

__device__ __forceinline__ float gelu_f(float x){
    return 0.5f*x*(1.0f + erff(x*0.70710678118654752440f));
}

/* ============================================================
   Kernel 1: per-(b,c) fused conv pipeline
   x[500] -> conv1(k9,p4)+BN+GELU -> maxpool2 -> conv2(64ch,k5,p2)+BN+GELU
          -> mean(t) -> proj(64->128) + elec_emb -> g_tok
   SMEM layout (floats):
     sx    [512]          @0
     sw1   [576]          @512
     sA1/B1/A2/B2 [4*64]  @1088
     sh1   [64*256]       @1344   (t padded: data at +2, float4 aligned)
     sw2   [320*65]       @17728  (transposed [ci*5+k][co], pad 65)
     spw   [64*129]       @38528  (proj_w transposed [c][d], pad 129)
     sh2   [64]           @46784
     spart [256]          @46848
   total 47104 floats = 188416 B
   ============================================================ */
__global__ __launch_bounds__(256) void conv_kernel(
    const float* __restrict__ x,
    const float* __restrict__ w1, const float* __restrict__ cb1,
    const float* __restrict__ g1, const float* __restrict__ be1,
    const float* __restrict__ m1, const float* __restrict__ v1,
    const float* __restrict__ w2, const float* __restrict__ cb2,
    const float* __restrict__ g2, const float* __restrict__ be2,
    const float* __restrict__ m2, const float* __restrict__ v2,
    const float* __restrict__ pw, const float* __restrict__ pb,
    const float* __restrict__ emb, float* __restrict__ tok)
{
    extern __shared__ float sm[];
    float* sx    = sm;
    float* sw1   = sm + 512;
    float* sA1   = sm + 1088;
    float* sB1   = sm + 1152;
    float* sA2   = sm + 1216;
    float* sB2   = sm + 1280;
    float* sh1   = sm + 1344;
    float* sw2   = sm + 17728;
    float* spw   = sm + 38528;
    float* sh2   = sm + 46784;
    float* spart = sm + 46848;

    const int bc  = blockIdx.x;
    const int tid = threadIdx.x;

    /* input row (pad 4 each side) */
    for (int i = tid; i < 512; i += 256) {
        int t = i - 4;
        sx[i] = (t >= 0 && t < Tn) ? x[bc*Tn + t] : 0.f;
    }
    for (int i = tid; i < COn*9; i += 256) sw1[i] = w1[i];
    if (tid < 64) {
        float a1 = g1[tid]*rsqrtf(v1[tid]+EPSf);
        sA1[tid] = a1;  sB1[tid] = (cb1[tid]-m1[tid])*a1 + be1[tid];
        float a2 = g2[tid]*rsqrtf(v2[tid]+EPSf);
        sA2[tid] = a2;  sB2[tid] = (cb2[tid]-m2[tid])*a2 + be2[tid];
    }
    /* conv2 weights: src [co][ci][k] (co*320+ci*5+k) -> sw2[(ci*5+k)*65+co] */
    for (int i = tid; i < COn*COn*5; i += 256) {
        int co = i / 320; int rest = i - co*320;
        sw2[rest*65 + co] = w2[i];
    }
    /* proj weights: src [d][c] -> spw[c*129+d] */
    for (int i = tid; i < Dn*COn; i += 256) {
        int d = i >> 6; int c = i & 63;
        spw[c*129 + d] = pw[i];
    }
    __syncthreads();

    /* conv1 + BN + GELU + maxpool(2) -> sh1[co][tp+2], tp in [0,250) */
    for (int i = tid; i < COn*250; i += 256) {
        int co = i / 250; int tp = i - co*250;
        const float* wp = &sw1[co*9];
        const float* xp = &sx[2*tp];
        float a0 = 0.f, a1 = 0.f;
        #pragma unroll
        for (int k = 0; k < 9; k++) { a0 += xp[k]*wp[k]; a1 += xp[k+1]*wp[k]; }
        float A = sA1[co], Bv = sB1[co];
        float y0 = gelu_f(a0*A + Bv);
        float y1 = gelu_f(a1*A + Bv);
        sh1[co*256 + 2 + tp] = fmaxf(y0, y1);
    }
    if (tid < 64) {
        sh1[tid*256 + 0]   = 0.f; sh1[tid*256 + 1]   = 0.f;
        sh1[tid*256 + 252] = 0.f; sh1[tid*256 + 253] = 0.f;
        sh1[tid*256 + 254] = 0.f; sh1[tid*256 + 255] = 0.f;
    }
    __syncthreads();

    /* conv2 + BN + GELU + mean over t.
       64 co-lanes x 4 t-groups; each thread 4 consecutive t per iter. */
    {
        const int co = tid & 63, tg = tid >> 6;
        const float A = sA2[co], Bv = sB2[co];
        float sum = 0.f;
        for (int iter = 0; iter < 16; iter++) {
            int t0 = iter*16 + tg*4;
            if (t0 >= 250) continue;
            float a0=0.f, a1=0.f, a2=0.f, a3=0.f;
            #pragma unroll 4
            for (int ci = 0; ci < 64; ci++) {
                const float4 hA = *(const float4*)&sh1[ci*256 + t0];
                const float4 hB = *(const float4*)&sh1[ci*256 + t0 + 4];
                const float* wp = &sw2[ci*5*65 + co];
                float w0 = wp[0], w1_ = wp[65], w2_ = wp[130], w3_ = wp[195], w4_ = wp[260];
                a0 += w0*hA.x + w1_*hA.y + w2_*hA.z + w3_*hA.w + w4_*hB.x;
                a1 += w0*hA.y + w1_*hA.z + w2_*hA.w + w3_*hB.x + w4_*hB.y;
                a2 += w0*hA.z + w1_*hA.w + w2_*hB.x + w3_*hB.y + w4_*hB.z;
                a3 += w0*hA.w + w1_*hB.x + w2_*hB.y + w3_*hB.z + w4_*hB.w;
            }
            sum += gelu_f(a0*A + Bv);
            if (t0+1 < 250) sum += gelu_f(a1*A + Bv);
            if (t0+2 < 250) sum += gelu_f(a2*A + Bv);
            if (t0+3 < 250) sum += gelu_f(a3*A + Bv);
        }
        spart[tg*64 + co] = sum;
    }
    __syncthreads();
    if (tid < 64)
        sh2[tid] = (spart[tid] + spart[64+tid] + spart[128+tid] + spart[192+tid]) * (1.f/250.f);
    __syncthreads();

    /* proj + elec_emb -> tok */
    if (tid < 128) {
        const int d = tid;
        float acc = pb[d];
        #pragma unroll 8
        for (int c = 0; c < 64; c++) acc += sh2[c]*spw[c*129 + d];
        int cidx = bc % Cn;
        tok[bc*Dn + d] = acc + emb[cidx*Dn + d];
    }
}

/* ============================================================
   Kernel 2: tiled GEMM  Y[M,N] = act(X[M,K] @ W[N,K]^T + bias)
   32 tokens/block, 256 threads, e-tiles of 64. M=7808=244*32.
   ============================================================ */
__global__ __launch_bounds__(256) void gemm_kernel(
    const float* __restrict__ X, const float* __restrict__ W,
    const float* __restrict__ bias, float* __restrict__ Y,
    int K, int N, int actGelu)
{
    extern __shared__ float sm[];
    float* sxT = sm;            /* [K][40] */
    float* swt = sm + K*40;     /* [K][65] */
    const int row0 = blockIdx.x*32;
    const int tid  = threadIdx.x;

    for (int li = tid; li < 32*K; li += 256) {
        int r = li / K, d = li - r*K;
        sxT[d*40 + r] = X[(row0+r)*K + d];
    }
    const int e_local = tid & 63, tg = tid >> 6;

    for (int e0 = 0; e0 < N; e0 += 64) {
        __syncthreads();
        for (int li = tid; li < 64*K; li += 256) {
            int e = li / K, d = li - e*K;
            swt[d*65 + e] = W[(e0+e)*K + d];
        }
        __syncthreads();
        float bb = bias[e0 + e_local];
        float acc[8];
        #pragma unroll
        for (int j = 0; j < 8; j++) acc[j] = bb;
        #pragma unroll 4
        for (int d = 0; d < K; d++) {
            float wv = swt[d*65 + e_local];
            const float4 ta = *(const float4*)&sxT[d*40 + tg*8];
            const float4 tb = *(const float4*)&sxT[d*40 + tg*8 + 4];
            acc[0] += ta.x*wv; acc[1] += ta.y*wv; acc[2] += ta.z*wv; acc[3] += ta.w*wv;
            acc[4] += tb.x*wv; acc[5] += tb.y*wv; acc[6] += tb.z*wv; acc[7] += tb.w*wv;
        }
        #pragma unroll
        for (int j = 0; j < 8; j++) {
            float v = acc[j];
            if (actGelu) v = gelu_f(v);
            Y[(row0 + tg*8 + j)*N + e0 + e_local] = v;
        }
    }
}

/* ============================================================
   Kernel 3: GEMM (N=128) + residual + LayerNorm epilogue
   Out = LN(Res + X @ W^T + bias)
   ============================================================ */
__global__ __launch_bounds__(256) void gemm_ln_kernel(
    const float* __restrict__ X, const float* __restrict__ W,
    const float* __restrict__ bias,
    const float* __restrict__ Res,
    const float* __restrict__ lng, const float* __restrict__ lnb,
    float* __restrict__ Out, int K)
{
    extern __shared__ float sm[];
    float* sxT = sm;               /* [K][40]  */
    float* swt = sm + K*40;        /* [K][65]  */
    float* sy  = swt + K*65;       /* [32][132] */
    const int row0 = blockIdx.x*32;
    const int tid  = threadIdx.x;

    for (int li = tid; li < 32*K; li += 256) {
        int r = li / K, d = li - r*K;
        sxT[d*40 + r] = X[(row0+r)*K + d];
    }
    const int e_local = tid & 63, tg = tid >> 6;

    for (int e0 = 0; e0 < 128; e0 += 64) {
        __syncthreads();
        for (int li = tid; li < 64*K; li += 256) {
            int e = li / K, d = li - e*K;
            swt[d*65 + e] = W[(e0+e)*K + d];
        }
        __syncthreads();
        float bb = bias[e0 + e_local];
        float acc[8];
        #pragma unroll
        for (int j = 0; j < 8; j++) acc[j] = bb;
        #pragma unroll 4
        for (int d = 0; d < K; d++) {
            float wv = swt[d*65 + e_local];
            const float4 ta = *(const float4*)&sxT[d*40 + tg*8];
            const float4 tb = *(const float4*)&sxT[d*40 + tg*8 + 4];
            acc[0] += ta.x*wv; acc[1] += ta.y*wv; acc[2] += ta.z*wv; acc[3] += ta.w*wv;
            acc[4] += tb.x*wv; acc[5] += tb.y*wv; acc[6] += tb.z*wv; acc[7] += tb.w*wv;
        }
        #pragma unroll
        for (int j = 0; j < 8; j++)
            sy[(tg*8 + j)*132 + e0 + e_local] = acc[j];
    }
    __syncthreads();

    /* residual + LN: warp w handles tokens w*4 .. w*4+3 */
    const int w = tid >> 5, lane = tid & 31;
    for (int q = 0; q < 4; q++) {
        int r = w*4 + q;
        float z[4]; float s1 = 0.f, s2 = 0.f;
        #pragma unroll
        for (int i = 0; i < 4; i++) {
            int idx = lane + 32*i;
            float zz = sy[r*132 + idx] + Res[(row0+r)*128 + idx];
            z[i] = zz; s1 += zz; s2 += zz*zz;
        }
        #pragma unroll
        for (int o = 16; o > 0; o >>= 1) {
            s1 += __shfl_xor_sync(0xffffffffu, s1, o);
            s2 += __shfl_xor_sync(0xffffffffu, s2, o);
        }
        float mean = s1*(1.f/128.f);
        float var  = s2*(1.f/128.f) - mean*mean;
        float rs   = rsqrtf(var + EPSf);
        #pragma unroll
        for (int i = 0; i < 4; i++) {
            int idx = lane + 32*i;
            Out[(row0+r)*128 + idx] = (z[i]-mean)*rs*lng[idx] + lnb[idx];
        }
    }
}

/* ============================================================
   Kernel 4: attention per (b, head). seq=122, dh=16.
   ============================================================ */
__global__ __launch_bounds__(128) void attn_kernel(
    const float* __restrict__ qkv, float* __restrict__ ctx)
{
    const int b = blockIdx.x >> 3, h = blockIdx.x & 7;
    extern __shared__ float sm[];
    float* sq = sm;                 /* [122][17] */
    float* sk = sm + 122*17;
    float* sv = sm + 2*122*17;
    float* sattb = sm + 3*122*17;   /* [4][128] */
    const int tid = threadIdx.x;

    for (int li = tid; li < 122*16; li += 128) {
        int s = li >> 4, d = li & 15;
        int base = (b*Cn + s)*384 + h*16 + d;
        sq[s*17 + d] = qkv[base];
        sk[s*17 + d] = qkv[base + 128];
        sv[s*17 + d] = qkv[base + 256];
    }
    __syncthreads();

    const int w = tid >> 5, lane = tid & 31;
    float* satt = sattb + w*128;

    for (int i = w; i < Cn; i += 4) {
        float sc[4];
        #pragma unroll
        for (int c = 0; c < 4; c++) {
            int kk = lane + 32*c;
            if (kk < Cn) {
                float s = 0.f;
                #pragma unroll
                for (int d = 0; d < 16; d++) s += sq[i*17 + d]*sk[kk*17 + d];
                sc[c] = s*0.25f;
            } else sc[c] = -1e30f;
        }
        float mx = fmaxf(fmaxf(sc[0], sc[1]), fmaxf(sc[2], sc[3]));
        #pragma unroll
        for (int o = 16; o > 0; o >>= 1) mx = fmaxf(mx, __shfl_xor_sync(0xffffffffu, mx, o));
        float p[4]; float sum = 0.f;
        #pragma unroll
        for (int c = 0; c < 4; c++) {
            int kk = lane + 32*c;
            p[c] = (kk < Cn) ? expf(sc[c]-mx) : 0.f;
            sum += p[c];
        }
        #pragma unroll
        for (int o = 16; o > 0; o >>= 1) sum += __shfl_xor_sync(0xffffffffu, sum, o);
        float inv = 1.f/sum;
        #pragma unroll
        for (int c = 0; c < 4; c++) {
            int kk = lane + 32*c;
            if (kk < Cn) satt[kk] = p[c]*inv;
        }
        __syncwarp();
        /* ctx: lanes 0-15 first half (j 0..60), lanes 16-31 second half */
        int d = lane & 15, half = lane >> 4;
        float a = 0.f;
        int j0 = half*61;
        for (int j = j0; j < j0 + 61; j++) a += satt[j]*sv[j*17 + d];
        a += __shfl_xor_sync(0xffffffffu, a, 16);
        if (lane < 16) ctx[(b*Cn + i)*Dn + h*16 + d] = a;
        __syncwarp();
    }
}

/* ============================================================
   Kernel 5: mean over C + per-subject head -> out[64,4]
   ============================================================ */
__global__ __launch_bounds__(128) void head_kernel(
    const float* __restrict__ tok, const int* __restrict__ sid,
    const float* __restrict__ hw, const float* __restrict__ hb,
    float* __restrict__ out)
{
    const int b = blockIdx.x;
    __shared__ float sp[128];
    const int d = threadIdx.x;
    float s = 0.f;
    for (int c = 0; c < Cn; c++) s += tok[(b*Cn + c)*Dn + d];
    sp[d] = s*(1.f/(float)Cn);
    __syncthreads();
    const int cls = threadIdx.x >> 5, lane = threadIdx.x & 31;
    const int sb = sid[b];
    float a = 0.f;
    #pragma unroll
    for (int i = 0; i < 4; i++) {
        int dd = lane + 32*i;
        a += sp[dd]*hw[(sb*4 + cls)*Dn + dd];
    }
    #pragma unroll
    for (int o = 16; o > 0; o >>= 1) a += __shfl_xor_sync(0xffffffffu, a, o);
    if (lane == 0) out[b*4 + cls] = a + hb[sb*4 + cls];
}

/* ============================================================ */
extern "C" void kernel_launch(void* const* d_in, const int* in_sizes, int n_in,
                              void* d_out, int out_size)
{
    const float* x       = (const float*)d_in[0];
    const int*   sid     = (const int*  )d_in[1];
    const float* conv1_w = (const float*)d_in[2];
    const float* conv1_b = (const float*)d_in[3];
    const float* bn1_g   = (const float*)d_in[4];
    const float* bn1_b   = (const float*)d_in[5];
    const float* bn1_m   = (const float*)d_in[6];
    const float* bn1_v   = (const float*)d_in[7];
    const float* conv2_w = (const float*)d_in[8];
    const float* conv2_b = (const float*)d_in[9];
    const float* bn2_g   = (const float*)d_in[10];
    const float* bn2_b   = (const float*)d_in[11];
    const float* bn2_m   = (const float*)d_in[12];
    const float* bn2_v   = (const float*)d_in[13];
    const float* proj_w  = (const float*)d_in[14];
    const float* proj_b  = (const float*)d_in[15];
    const float* emb     = (const float*)d_in[16];
    const float* qkv_w   = (const float*)d_in[17];
    const float* qkv_b   = (const float*)d_in[18];
    const float* out_w   = (const float*)d_in[19];
    const float* out_b   = (const float*)d_in[20];
    const float* ln1_g   = (const float*)d_in[21];
    const float* ln1_b   = (const float*)d_in[22];
    const float* ff1_w   = (const float*)d_in[23];
    const float* ff1_b   = (const float*)d_in[24];
    const float* ff2_w   = (const float*)d_in[25];
    const float* ff2_b   = (const float*)d_in[26];
    const float* ln2_g   = (const float*)d_in[27];
    const float* ln2_b   = (const float*)d_in[28];
    const float* heads_w = (const float*)d_in[29];
    const float* heads_b = (const float*)d_in[30];

    const int CONV_SMEM   = 47104*4;                       /* 188416 B */
    const int GEMM_SMEM   = (128*40 + 128*65)*4;           /* 53760 B  */
    const int GLN_SMEM128 = (128*40 + 128*65 + 32*132)*4;  /* 70656 B  */
    const int GLN_SMEM256 = (256*40 + 256*65 + 32*132)*4;  /* 124416 B */
    const int ATTN_SMEM   = (3*122*17 + 4*128)*4;          /* 26936 B  */

    cudaFuncSetAttribute(conv_kernel,    cudaFuncAttributeMaxDynamicSharedMemorySize, CONV_SMEM);
    cudaFuncSetAttribute(gemm_kernel,    cudaFuncAttributeMaxDynamicSharedMemorySize, GEMM_SMEM);
    cudaFuncSetAttribute(gemm_ln_kernel, cudaFuncAttributeMaxDynamicSharedMemorySize, GLN_SMEM256);

    float* tokp = nullptr; float* qkvp = nullptr; float* ctxp = nullptr; float* ffp = nullptr;
    cudaGetSymbolAddress((void**)&tokp, g_tok);
    cudaGetSymbolAddress((void**)&qkvp, g_qkv);
    cudaGetSymbolAddress((void**)&ctxp, g_ctx);
    cudaGetSymbolAddress((void**)&ffp,  g_ff);

    conv_kernel<<<BC, 256, CONV_SMEM>>>(
        x, conv1_w, conv1_b, bn1_g, bn1_b, bn1_m, bn1_v,
        conv2_w, conv2_b, bn2_g, bn2_b, bn2_m, bn2_v,
        proj_w, proj_b, emb, tokp);

    for (int l = 0; l < Lln; l++) {
        gemm_kernel<<<244, 256, GEMM_SMEM>>>(
            tokp, qkv_w + l*3*Dn*Dn, qkv_b + l*3*Dn, qkvp, Dn, 3*Dn, 0);
        attn_kernel<<<Bn*Hn, 128, ATTN_SMEM>>>(qkvp, ctxp);
        gemm_ln_kernel<<<244, 256, GLN_SMEM128>>>(
            ctxp, out_w + l*Dn*Dn, out_b + l*Dn,
            tokp, ln1_g + l*Dn, ln1_b + l*Dn, tokp, Dn);
        gemm_kernel<<<244, 256, GEMM_SMEM>>>(
            tokp, ff1_w + l*FFn*Dn, ff1_b + l*FFn, ffp, Dn, FFn, 1);
        gemm_ln_kernel<<<244, 256, GLN_SMEM256>>>(
            ffp, ff2_w + l*Dn*FFn, ff2_b + l*Dn,
            tokp, ln2_g + l*Dn, ln2_b + l*Dn, tokp, FFn);
    }

    head_kernel<<<Bn, 128>>>(tokp, sid, heads_w, heads_b, (float*)d_out);
}

// round 2
// speedup vs baseline: 1.2547x; 1.2547x over previous
#include <cuda_runtime.h>

#define Bn   64
#define Cn   122
#define Tn   500
#define COn  64
#define Dn   128
#define Hn   8
#define FFn  256
#define Lln  2
#define BC   (Bn*Cn)        /* 7808 = 244*32 */
#define EPSf 1e-5f

typedef unsigned long long ull;

/* ---------------- scratch (device globals; no allocation) ---------------- */
__device__ float g_tok[BC*Dn];
__device__ float g_qkv[BC*3*Dn];
__device__ float g_ctx[BC*Dn];
__device__ float g_ff [BC*FFn];

__device__ __forceinline__ float gelu_f(float x){
    return 0.5f*x*(1.0f + erff(x*0.70710678118654752440f));
}

/* packed f32x2 helpers (sm_100+) */
__device__ __forceinline__ ull pk(float a, float b){
    ull r; asm("mov.b64 %0, {%1, %2};" : "=l"(r) : "f"(a), "f"(b)); return r;
}
__device__ __forceinline__ void fma2(ull& d, ull a, ull b){
    asm("fma.rn.f32x2 %0, %1, %2, %0;" : "+l"(d) : "l"(a), "l"(b));
}
__device__ __forceinline__ float2 upk(ull a){
    float2 f; asm("mov.b64 {%0, %1}, %2;" : "=f"(f.x), "=f"(f.y) : "l"(a)); return f;
}

/* ============================================================
   Kernel 1: per-(b,c) fused conv pipeline, 512 threads.
   x[500] -> conv1(k9,p4)+BN+GELU -> maxpool2 -> conv2(64ch,k5,p2)+BN+GELU
          -> mean(t) -> proj(64->128) + elec_emb -> g_tok
   SMEM (floats):
     sx[512]@0  sw1[576]@512  sA1/B1/A2/B2@1088..1344
     sh1[64*256]@1344 (t data at +2)
     sw2[320*64]@17728 (transposed [ci*5+k][co])
     spw[64*129]@38208  sh2[64]@46464  spart[512]@46528
   total 47040 floats = 188160 B
   ============================================================ */
__global__ __launch_bounds__(512) void conv_kernel(
    const float* __restrict__ x,
    const float* __restrict__ w1, const float* __restrict__ cb1,
    const float* __restrict__ g1, const float* __restrict__ be1,
    const float* __restrict__ m1, const float* __restrict__ v1,
    const float* __restrict__ w2, const float* __restrict__ cb2,
    const float* __restrict__ g2, const float* __restrict__ be2,
    const float* __restrict__ m2, const float* __restrict__ v2,
    const float* __restrict__ pw, const float* __restrict__ pb,
    const float* __restrict__ emb, float* __restrict__ tok)
{
    extern __shared__ float sm[];
    float* sx    = sm;
    float* sw1   = sm + 512;
    float* sA1   = sm + 1088;
    float* sB1   = sm + 1152;
    float* sA2   = sm + 1216;
    float* sB2   = sm + 1280;
    float* sh1   = sm + 1344;
    float* sw2   = sm + 17728;
    float* spw   = sm + 38208;
    float* sh2   = sm + 46464;
    float* spart = sm + 46528;

    const int bc  = blockIdx.x;
    const int tid = threadIdx.x;

    for (int i = tid; i < 512; i += 512) {
        int t = i - 4;
        sx[i] = (t >= 0 && t < Tn) ? x[bc*Tn + t] : 0.f;
    }
    for (int i = tid; i < COn*9; i += 512) sw1[i] = w1[i];
    if (tid < 64) {
        float a1 = g1[tid]*rsqrtf(v1[tid]+EPSf);
        sA1[tid] = a1;  sB1[tid] = (cb1[tid]-m1[tid])*a1 + be1[tid];
        float a2 = g2[tid]*rsqrtf(v2[tid]+EPSf);
        sA2[tid] = a2;  sB2[tid] = (cb2[tid]-m2[tid])*a2 + be2[tid];
    }
    /* conv2 weights: src [co][ci][k] -> sw2[(ci*5+k)*64+co] */
    for (int i = tid; i < COn*COn*5; i += 512) {
        int co = i / 320; int rest = i - co*320;
        sw2[rest*64 + co] = w2[i];
    }
    /* proj weights: src [d][c] -> spw[c*129+d] */
    for (int i = tid; i < Dn*COn; i += 512) {
        int d = i >> 6; int c = i & 63;
        spw[c*129 + d] = pw[i];
    }
    __syncthreads();

    /* conv1 + BN + GELU + maxpool(2) -> sh1[co][tp+2] */
    for (int i = tid; i < COn*250; i += 512) {
        int co = i / 250; int tp = i - co*250;
        const float* wp = &sw1[co*9];
        const float* xp = &sx[2*tp];
        float a0 = 0.f, a1 = 0.f;
        #pragma unroll
        for (int k = 0; k < 9; k++) { a0 += xp[k]*wp[k]; a1 += xp[k+1]*wp[k]; }
        float A = sA1[co], Bv = sB1[co];
        float y0 = gelu_f(a0*A + Bv);
        float y1 = gelu_f(a1*A + Bv);
        sh1[co*256 + 2 + tp] = fmaxf(y0, y1);
    }
    if (tid < 64) {
        sh1[tid*256 + 0]   = 0.f; sh1[tid*256 + 1]   = 0.f;
        sh1[tid*256 + 252] = 0.f; sh1[tid*256 + 253] = 0.f;
        sh1[tid*256 + 254] = 0.f; sh1[tid*256 + 255] = 0.f;
    }
    __syncthreads();

    /* conv2 + BN + GELU + mean over t, packed f32x2.
       64 co-lanes x 8 t-groups; thread owns 16 t per pass, 2 passes. */
    {
        const int co = tid & 63, tg = tid >> 6;       /* tg 0..7 */
        const float A = sA2[co], Bv = sB2[co];
        float sum = 0.f;
        for (int pass = 0; pass < 2; pass++) {
            const int t0 = pass*128 + tg*16;          /* 0..240 step 16 */
            ull acc[8];
            #pragma unroll
            for (int j = 0; j < 8; j++) acc[j] = 0ULL;
            for (int ci = 0; ci < 64; ci++) {
                const float* hp = &sh1[ci*256 + t0];
                float4 q0 = *(const float4*)(hp +  0);
                float4 q1 = *(const float4*)(hp +  4);
                float4 q2 = *(const float4*)(hp +  8);
                float4 q3 = *(const float4*)(hp + 12);
                float4 q4 = *(const float4*)(hp + 16);
                float v[20] = {q0.x,q0.y,q0.z,q0.w, q1.x,q1.y,q1.z,q1.w,
                               q2.x,q2.y,q2.z,q2.w, q3.x,q3.y,q3.z,q3.w,
                               q4.x,q4.y,q4.z,q4.w};
                const float* wp = &sw2[(ci*5)*64 + co];
                ull W0 = pk(wp[0],   wp[0]);
                ull W1 = pk(wp[64],  wp[64]);
                ull W2 = pk(wp[128], wp[128]);
                ull W3 = pk(wp[192], wp[192]);
                ull W4 = pk(wp[256], wp[256]);
                ull Pe[10], Po[9];
                #pragma unroll
                for (int j = 0; j < 10; j++) Pe[j] = pk(v[2*j], v[2*j+1]);
                #pragma unroll
                for (int j = 0; j < 9; j++)  Po[j] = pk(v[2*j+1], v[2*j+2]);
                #pragma unroll
                for (int j = 0; j < 8; j++) {
                    fma2(acc[j], W0, Pe[j]);
                    fma2(acc[j], W1, Po[j]);
                    fma2(acc[j], W2, Pe[j+1]);
                    fma2(acc[j], W3, Po[j+1]);
                    fma2(acc[j], W4, Pe[j+2]);
                }
            }
            #pragma unroll
            for (int j = 0; j < 8; j++) {
                float2 y = upk(acc[j]);
                int t = t0 + 2*j;
                if (t     < 250) sum += gelu_f(y.x*A + Bv);
                if (t + 1 < 250) sum += gelu_f(y.y*A + Bv);
            }
        }
        spart[tg*64 + co] = sum;
    }
    __syncthreads();
    if (tid < 64) {
        float s = 0.f;
        #pragma unroll
        for (int g = 0; g < 8; g++) s += spart[g*64 + tid];
        sh2[tid] = s * (1.f/250.f);
    }
    __syncthreads();

    /* proj + elec_emb -> tok */
    if (tid < 128) {
        const int d = tid;
        float acc = pb[d];
        #pragma unroll 8
        for (int c = 0; c < 64; c++) acc += sh2[c]*spw[c*129 + d];
        int cidx = bc % Cn;
        tok[bc*Dn + d] = acc + emb[cidx*Dn + d];
    }
}

/* ============================================================
   Kernel 2: tiled GEMM  Y[M,N] = act(X[M,K] @ W[N,K]^T + bias)
   32 tokens x 64 outputs per block (blockIdx.y = e-tile). f32x2.
   ============================================================ */
__global__ __launch_bounds__(256) void gemm_kernel(
    const float* __restrict__ X, const float* __restrict__ W,
    const float* __restrict__ bias, float* __restrict__ Y,
    int K, int N, int actGelu)
{
    extern __shared__ float sm[];
    float* sxT = sm;            /* [K][40] */
    float* swt = sm + K*40;     /* [K][65] */
    const int row0 = blockIdx.x*32;
    const int e0   = blockIdx.y*64;
    const int tid  = threadIdx.x;

    for (int li = tid; li < 32*K; li += 256) {
        int r = li / K, d = li - r*K;
        sxT[d*40 + r] = X[(row0+r)*K + d];
    }
    for (int li = tid; li < 64*K; li += 256) {
        int e = li / K, d = li - e*K;
        swt[d*65 + e] = W[(e0+e)*K + d];
    }
    __syncthreads();

    const int e_local = tid & 63, tg = tid >> 6;
    float bb = bias[e0 + e_local];
    ull acc[4];
    #pragma unroll
    for (int j = 0; j < 4; j++) acc[j] = pk(bb, bb);
    #pragma unroll 4
    for (int d = 0; d < K; d++) {
        ull Wp = pk(swt[d*65 + e_local], swt[d*65 + e_local]);
        const ull* tp = (const ull*)&sxT[d*40 + tg*8];
        fma2(acc[0], Wp, tp[0]);
        fma2(acc[1], Wp, tp[1]);
        fma2(acc[2], Wp, tp[2]);
        fma2(acc[3], Wp, tp[3]);
    }
    #pragma unroll
    for (int j = 0; j < 4; j++) {
        float2 y = upk(acc[j]);
        if (actGelu) { y.x = gelu_f(y.x); y.y = gelu_f(y.y); }
        Y[(row0 + tg*8 + 2*j  )*N + e0 + e_local] = y.x;
        Y[(row0 + tg*8 + 2*j+1)*N + e0 + e_local] = y.y;
    }
}

/* ============================================================
   Kernel 3: GEMM (N=128) + residual + LayerNorm epilogue, f32x2
   ============================================================ */
__global__ __launch_bounds__(256) void gemm_ln_kernel(
    const float* __restrict__ X, const float* __restrict__ W,
    const float* __restrict__ bias,
    const float* __restrict__ Res,
    const float* __restrict__ lng, const float* __restrict__ lnb,
    float* __restrict__ Out, int K)
{
    extern __shared__ float sm[];
    float* sxT = sm;               /* [K][40]  */
    float* swt = sm + K*40;        /* [K][65]  */
    float* sy  = swt + K*65;       /* [32][132] */
    const int row0 = blockIdx.x*32;
    const int tid  = threadIdx.x;

    for (int li = tid; li < 32*K; li += 256) {
        int r = li / K, d = li - r*K;
        sxT[d*40 + r] = X[(row0+r)*K + d];
    }
    const int e_local = tid & 63, tg = tid >> 6;

    for (int e0 = 0; e0 < 128; e0 += 64) {
        __syncthreads();
        for (int li = tid; li < 64*K; li += 256) {
            int e = li / K, d = li - e*K;
            swt[d*65 + e] = W[(e0+e)*K + d];
        }
        __syncthreads();
        float bb = bias[e0 + e_local];
        ull acc[4];
        #pragma unroll
        for (int j = 0; j < 4; j++) acc[j] = pk(bb, bb);
        #pragma unroll 4
        for (int d = 0; d < K; d++) {
            ull Wp = pk(swt[d*65 + e_local], swt[d*65 + e_local]);
            const ull* tp = (const ull*)&sxT[d*40 + tg*8];
            fma2(acc[0], Wp, tp[0]);
            fma2(acc[1], Wp, tp[1]);
            fma2(acc[2], Wp, tp[2]);
            fma2(acc[3], Wp, tp[3]);
        }
        #pragma unroll
        for (int j = 0; j < 4; j++) {
            float2 y = upk(acc[j]);
            sy[(tg*8 + 2*j  )*132 + e0 + e_local] = y.x;
            sy[(tg*8 + 2*j+1)*132 + e0 + e_local] = y.y;
        }
    }
    __syncthreads();

    const int w = tid >> 5, lane = tid & 31;
    for (int q = 0; q < 4; q++) {
        int r = w*4 + q;
        float z[4]; float s1 = 0.f, s2 = 0.f;
        #pragma unroll
        for (int i = 0; i < 4; i++) {
            int idx = lane + 32*i;
            float zz = sy[r*132 + idx] + Res[(row0+r)*128 + idx];
            z[i] = zz; s1 += zz; s2 += zz*zz;
        }
        #pragma unroll
        for (int o = 16; o > 0; o >>= 1) {
            s1 += __shfl_xor_sync(0xffffffffu, s1, o);
            s2 += __shfl_xor_sync(0xffffffffu, s2, o);
        }
        float mean = s1*(1.f/128.f);
        float var  = s2*(1.f/128.f) - mean*mean;
        float rs   = rsqrtf(var + EPSf);
        #pragma unroll
        for (int i = 0; i < 4; i++) {
            int idx = lane + 32*i;
            Out[(row0+r)*128 + idx] = (z[i]-mean)*rs*lng[idx] + lnb[idx];
        }
    }
}

/* ============================================================
   Kernel 4: attention per (b, head). seq=122, dh=16.
   ============================================================ */
__global__ __launch_bounds__(128) void attn_kernel(
    const float* __restrict__ qkv, float* __restrict__ ctx)
{
    const int b = blockIdx.x >> 3, h = blockIdx.x & 7;
    extern __shared__ float sm[];
    float* sq = sm;                 /* [122][17] */
    float* sk = sm + 122*17;
    float* sv = sm + 2*122*17;
    float* sattb = sm + 3*122*17;   /* [4][128] */
    const int tid = threadIdx.x;

    for (int li = tid; li < 122*16; li += 128) {
        int s = li >> 4, d = li & 15;
        int base = (b*Cn + s)*384 + h*16 + d;
        sq[s*17 + d] = qkv[base];
        sk[s*17 + d] = qkv[base + 128];
        sv[s*17 + d] = qkv[base + 256];
    }
    __syncthreads();

    const int w = tid >> 5, lane = tid & 31;
    float* satt = sattb + w*128;

    for (int i = w; i < Cn; i += 4) {
        float sc[4];
        #pragma unroll
        for (int c = 0; c < 4; c++) {
            int kk = lane + 32*c;
            if (kk < Cn) {
                float s = 0.f;
                #pragma unroll
                for (int d = 0; d < 16; d++) s += sq[i*17 + d]*sk[kk*17 + d];
                sc[c] = s*0.25f;
            } else sc[c] = -1e30f;
        }
        float mx = fmaxf(fmaxf(sc[0], sc[1]), fmaxf(sc[2], sc[3]));
        #pragma unroll
        for (int o = 16; o > 0; o >>= 1) mx = fmaxf(mx, __shfl_xor_sync(0xffffffffu, mx, o));
        float p[4]; float sum = 0.f;
        #pragma unroll
        for (int c = 0; c < 4; c++) {
            int kk = lane + 32*c;
            p[c] = (kk < Cn) ? expf(sc[c]-mx) : 0.f;
            sum += p[c];
        }
        #pragma unroll
        for (int o = 16; o > 0; o >>= 1) sum += __shfl_xor_sync(0xffffffffu, sum, o);
        float inv = 1.f/sum;
        #pragma unroll
        for (int c = 0; c < 4; c++) {
            int kk = lane + 32*c;
            if (kk < Cn) satt[kk] = p[c]*inv;
        }
        __syncwarp();
        int d = lane & 15, half = lane >> 4;
        float a = 0.f;
        int j0 = half*61;
        for (int j = j0; j < j0 + 61; j++) a += satt[j]*sv[j*17 + d];
        a += __shfl_xor_sync(0xffffffffu, a, 16);
        if (lane < 16) ctx[(b*Cn + i)*Dn + h*16 + d] = a;
        __syncwarp();
    }
}

/* ============================================================
   Kernel 5: mean over C + per-subject head -> out[64,4]
   ============================================================ */
__global__ __launch_bounds__(128) void head_kernel(
    const float* __restrict__ tok, const int* __restrict__ sid,
    const float* __restrict__ hw, const float* __restrict__ hb,
    float* __restrict__ out)
{
    const int b = blockIdx.x;
    __shared__ float sp[128];
    const int d = threadIdx.x;
    float s = 0.f;
    for (int c = 0; c < Cn; c++) s += tok[(b*Cn + c)*Dn + d];
    sp[d] = s*(1.f/(float)Cn);
    __syncthreads();
    const int cls = threadIdx.x >> 5, lane = threadIdx.x & 31;
    const int sb = sid[b];
    float a = 0.f;
    #pragma unroll
    for (int i = 0; i < 4; i++) {
        int dd = lane + 32*i;
        a += sp[dd]*hw[(sb*4 + cls)*Dn + dd];
    }
    #pragma unroll
    for (int o = 16; o > 0; o >>= 1) a += __shfl_xor_sync(0xffffffffu, a, o);
    if (lane == 0) out[b*4 + cls] = a + hb[sb*4 + cls];
}

/* ============================================================ */
extern "C" void kernel_launch(void* const* d_in, const int* in_sizes, int n_in,
                              void* d_out, int out_size)
{
    const float* x       = (const float*)d_in[0];
    const int*   sid     = (const int*  )d_in[1];
    const float* conv1_w = (const float*)d_in[2];
    const float* conv1_b = (const float*)d_in[3];
    const float* bn1_g   = (const float*)d_in[4];
    const float* bn1_b   = (const float*)d_in[5];
    const float* bn1_m   = (const float*)d_in[6];
    const float* bn1_v   = (const float*)d_in[7];
    const float* conv2_w = (const float*)d_in[8];
    const float* conv2_b = (const float*)d_in[9];
    const float* bn2_g   = (const float*)d_in[10];
    const float* bn2_b   = (const float*)d_in[11];
    const float* bn2_m   = (const float*)d_in[12];
    const float* bn2_v   = (const float*)d_in[13];
    const float* proj_w  = (const float*)d_in[14];
    const float* proj_b  = (const float*)d_in[15];
    const float* emb     = (const float*)d_in[16];
    const float* qkv_w   = (const float*)d_in[17];
    const float* qkv_b   = (const float*)d_in[18];
    const float* out_w   = (const float*)d_in[19];
    const float* out_b   = (const float*)d_in[20];
    const float* ln1_g   = (const float*)d_in[21];
    const float* ln1_b   = (const float*)d_in[22];
    const float* ff1_w   = (const float*)d_in[23];
    const float* ff1_b   = (const float*)d_in[24];
    const float* ff2_w   = (const float*)d_in[25];
    const float* ff2_b   = (const float*)d_in[26];
    const float* ln2_g   = (const float*)d_in[27];
    const float* ln2_b   = (const float*)d_in[28];
    const float* heads_w = (const float*)d_in[29];
    const float* heads_b = (const float*)d_in[30];

    const int CONV_SMEM   = 47040*4;                       /* 188160 B */
    const int GEMM_SMEM   = (128*40 + 128*65)*4;           /* 53760 B  */
    const int GLN_SMEM128 = (128*40 + 128*65 + 32*132)*4;  /* 70656 B  */
    const int GLN_SMEM256 = (256*40 + 256*65 + 32*132)*4;  /* 124416 B */
    const int ATTN_SMEM   = (3*122*17 + 4*128)*4;          /* 26936 B  */

    cudaFuncSetAttribute(conv_kernel,    cudaFuncAttributeMaxDynamicSharedMemorySize, CONV_SMEM);
    cudaFuncSetAttribute(gemm_kernel,    cudaFuncAttributeMaxDynamicSharedMemorySize, GEMM_SMEM);
    cudaFuncSetAttribute(gemm_ln_kernel, cudaFuncAttributeMaxDynamicSharedMemorySize, GLN_SMEM256);

    float* tokp = nullptr; float* qkvp = nullptr; float* ctxp = nullptr; float* ffp = nullptr;
    cudaGetSymbolAddress((void**)&tokp, g_tok);
    cudaGetSymbolAddress((void**)&qkvp, g_qkv);
    cudaGetSymbolAddress((void**)&ctxp, g_ctx);
    cudaGetSymbolAddress((void**)&ffp,  g_ff);

    conv_kernel<<<BC, 512, CONV_SMEM>>>(
        x, conv1_w, conv1_b, bn1_g, bn1_b, bn1_m, bn1_v,
        conv2_w, conv2_b, bn2_g, bn2_b, bn2_m, bn2_v,
        proj_w, proj_b, emb, tokp);

    for (int l = 0; l < Lln; l++) {
        gemm_kernel<<<dim3(244, 6), 256, GEMM_SMEM>>>(
            tokp, qkv_w + l*3*Dn*Dn, qkv_b + l*3*Dn, qkvp, Dn, 3*Dn, 0);
        attn_kernel<<<Bn*Hn, 128, ATTN_SMEM>>>(qkvp, ctxp);
        gemm_ln_kernel<<<244, 256, GLN_SMEM128>>>(
            ctxp, out_w + l*Dn*Dn, out_b + l*Dn,
            tokp, ln1_g + l*Dn, ln1_b + l*Dn, tokp, Dn);
        gemm_kernel<<<dim3(244, 4), 256, GEMM_SMEM>>>(
            tokp, ff1_w + l*FFn*Dn, ff1_b + l*FFn, ffp, Dn, FFn, 1);
        gemm_ln_kernel<<<244, 256, GLN_SMEM256>>>(
            ffp, ff2_w + l*Dn*FFn, ff2_b + l*Dn,
            tokp, ln2_g + l*Dn, ln2_b + l*Dn, tokp, FFn);
    }

    head_kernel<<<Bn, 128>>>(tokp, sid, heads_w, heads_b, (float*)d_out);
}

// round 3
// speedup vs baseline: 1.2788x; 1.0192x over previous
#include <cuda_runtime.h>

#define Bn   64
#define Cn   122
#define Tn   500
#define COn  64
#define Dn   128
#define Hn   8
#define FFn  256
#define Lln  2
#define BC   (Bn*Cn)        /* 7808 = 244*32 */
#define EPSf 1e-5f

typedef unsigned long long ull;

/* ---------------- scratch (device globals; no allocation) ---------------- */
__device__ float g_tok[BC*Dn];
__device__ float g_qkv[BC*3*Dn];
__device__ float g_ctx[BC*Dn];
__device__ float g_ff [BC*FFn];

__device__ __forceinline__ float gelu_f(float x){
    return 0.5f*x*(1.0f + erff(x*0.70710678118654752440f));
}

/* packed f32x2 helpers (sm_100+) */
__device__ __forceinline__ ull pk(float a, float b){
    ull r; asm("mov.b64 %0, {%1, %2};" : "=l"(r) : "f"(a), "f"(b)); return r;
}
__device__ __forceinline__ void fma2(ull& d, ull a, ull b){
    asm("fma.rn.f32x2 %0, %1, %2, %0;" : "+l"(d) : "l"(a), "l"(b));
}
__device__ __forceinline__ float2 upk(ull a){
    float2 f; asm("mov.b64 {%0, %1}, %2;" : "=f"(f.x), "=f"(f.y) : "l"(a)); return f;
}

/* ============================================================
   Kernel 1: per-(b,c) fused conv pipeline, 512 threads.
   All conv2 FFMA2 operands come straight from SMEM (no packs):
     sh1d: conv1 output duplicated as (h,h) f32x2 pairs, row 264 ull
           (pad 2 front / >=10 back, zeros), 16B-aligned windows.
     sw2p: conv2 weights as float2(w[coh], w[coh+32]), [ci*5+k][coh].
   SMEM (bytes):
     sh1d @0        64*264*8 = 135168
     sw2p @135168   320*32*8 =  81920   (ends 217088)
     sx   @217088   512*4    =   2048
     sw1  @219136   576*4    =   2304
     sA1  @221440   64*4  sB1 sA2 sB2 (1024 total)
     spart@222464   1024*4   =   4096
     sh2  @226560   64*4     =    256   (total 226816 <= 232448)
   ============================================================ */
__global__ __launch_bounds__(512) void conv_kernel(
    const float* __restrict__ x,
    const float* __restrict__ w1, const float* __restrict__ cb1,
    const float* __restrict__ g1, const float* __restrict__ be1,
    const float* __restrict__ m1, const float* __restrict__ v1,
    const float* __restrict__ w2, const float* __restrict__ cb2,
    const float* __restrict__ g2, const float* __restrict__ be2,
    const float* __restrict__ m2, const float* __restrict__ v2,
    const float* __restrict__ pw, const float* __restrict__ pb,
    const float* __restrict__ emb, float* __restrict__ tok)
{
    extern __shared__ char smraw[];
    ull*   sh1d  = (ull*)(smraw);                 /* [64][264] pairs */
    ull*   sw2p  = (ull*)(smraw + 135168);        /* [320][32] pairs */
    float* sx    = (float*)(smraw + 217088);
    float* sw1   = (float*)(smraw + 219136);
    float* sA1   = (float*)(smraw + 221440);
    float* sB1   = sA1 + 64;
    float* sA2   = sA1 + 128;
    float* sB2   = sA1 + 192;
    float* spart = (float*)(smraw + 222464);      /* [16][64] */
    float* sh2   = (float*)(smraw + 226560);

    const int bc  = blockIdx.x;
    const int tid = threadIdx.x;

    if (tid < 512) {
        int t = tid - 4;
        sx[tid] = (t >= 0 && t < Tn) ? x[bc*Tn + t] : 0.f;
    }
    for (int i = tid; i < COn*9; i += 512) sw1[i] = w1[i];
    if (tid < 64) {
        float a1 = g1[tid]*rsqrtf(v1[tid]+EPSf);
        sA1[tid] = a1;  sB1[tid] = (cb1[tid]-m1[tid])*a1 + be1[tid];
        float a2 = g2[tid]*rsqrtf(v2[tid]+EPSf);
        sA2[tid] = a2;  sB2[tid] = (cb2[tid]-m2[tid])*a2 + be2[tid];
    }
    /* conv2 weights -> co-pair layout: sw2p[rest*32+coh] = (w[coh][rest], w[coh+32][rest]) */
    for (int i = tid; i < 32*COn*5; i += 512) {
        int coh = i & 31; int rest = i >> 5;      /* rest = ci*5+k */
        float lo = w2[coh*320 + rest];
        float hi = w2[(coh+32)*320 + rest];
        sw2p[rest*32 + coh] = pk(lo, hi);
    }
    /* zero padding of sh1d rows: j in {0,1} and {252..263} */
    for (int i = tid; i < 64*14; i += 512) {
        int row = i / 14, j = i % 14;
        int col = (j < 2) ? j : (250 + j);
        sh1d[row*264 + col] = 0ULL;
    }
    __syncthreads();

    /* conv1 + BN + GELU + maxpool(2) -> sh1d[co][2+tp] = (m,m) */
    for (int i = tid; i < COn*250; i += 512) {
        int co = i / 250; int tp = i - co*250;
        const float* wp = &sw1[co*9];
        const float* xp = &sx[2*tp];
        float a0 = 0.f, a1 = 0.f;
        #pragma unroll
        for (int k = 0; k < 9; k++) { a0 += xp[k]*wp[k]; a1 += xp[k+1]*wp[k]; }
        float A = sA1[co], Bv = sB1[co];
        float y0 = gelu_f(a0*A + Bv);
        float y1 = gelu_f(a1*A + Bv);
        float m  = fmaxf(y0, y1);
        sh1d[co*264 + 2 + tp] = pk(m, m);
    }
    __syncthreads();

    /* conv2 + BN + GELU + mean over t, pure-SMEM-operand f32x2.
       coh = tid&31 -> co pair {coh, coh+32}; tg = tid>>5 -> t0 = tg*16. */
    {
        const int coh = tid & 31, tg = tid >> 5;
        const int t0 = tg*16;
        ull acc[16];
        #pragma unroll
        for (int j = 0; j < 16; j++) acc[j] = 0ULL;

        for (int ci = 0; ci < 64; ci++) {
            ull vv[20];
            const ulonglong2* hp = (const ulonglong2*)&sh1d[ci*264 + t0];
            #pragma unroll
            for (int j = 0; j < 10; j++) {
                ulonglong2 p = hp[j];
                vv[2*j] = p.x; vv[2*j+1] = p.y;
            }
            const ull* wp = &sw2p[(ci*5)*32 + coh];
            #pragma unroll
            for (int k = 0; k < 5; k++) {
                ull W = wp[k*32];
                #pragma unroll
                for (int t = 0; t < 16; t++) fma2(acc[t], W, vv[t+k]);
            }
        }
        const float Alo = sA2[coh],    Blo = sB2[coh];
        const float Ahi = sA2[coh+32], Bhi = sB2[coh+32];
        float slo = 0.f, shi = 0.f;
        #pragma unroll
        for (int t = 0; t < 16; t++) {
            if (t0 + t < 250) {
                float2 y = upk(acc[t]);
                slo += gelu_f(y.x*Alo + Blo);
                shi += gelu_f(y.y*Ahi + Bhi);
            }
        }
        spart[tg*64 + coh]      = slo;
        spart[tg*64 + coh + 32] = shi;
    }
    __syncthreads();
    if (tid < 64) {
        float s = 0.f;
        #pragma unroll
        for (int g = 0; g < 16; g++) s += spart[g*64 + tid];
        sh2[tid] = s * (1.f/250.f);
    }
    __syncthreads();

    /* proj + elec_emb -> tok (proj weights streamed from gmem/L2) */
    if (tid < 128) {
        const int d = tid;
        float acc = pb[d];
        const float* pwr = &pw[d*COn];
        #pragma unroll 8
        for (int c = 0; c < 64; c++) acc += sh2[c]*__ldg(&pwr[c]);
        int cidx = bc % Cn;
        tok[bc*Dn + d] = acc + emb[cidx*Dn + d];
    }
}

/* ============================================================
   Kernel 2: tiled GEMM  Y[M,N] = act(X[M,K] @ W[N,K]^T + bias)
   32 tokens x 64 outputs per block (blockIdx.y = e-tile). f32x2.
   ============================================================ */
__global__ __launch_bounds__(256) void gemm_kernel(
    const float* __restrict__ X, const float* __restrict__ W,
    const float* __restrict__ bias, float* __restrict__ Y,
    int K, int N, int actGelu)
{
    extern __shared__ float sm[];
    float* sxT = sm;            /* [K][40] */
    float* swt = sm + K*40;     /* [K][65] */
    const int row0 = blockIdx.x*32;
    const int e0   = blockIdx.y*64;
    const int tid  = threadIdx.x;

    for (int li = tid; li < 32*K; li += 256) {
        int r = li / K, d = li - r*K;
        sxT[d*40 + r] = X[(row0+r)*K + d];
    }
    for (int li = tid; li < 64*K; li += 256) {
        int e = li / K, d = li - e*K;
        swt[d*65 + e] = W[(e0+e)*K + d];
    }
    __syncthreads();

    const int e_local = tid & 63, tg = tid >> 6;
    float bb = bias[e0 + e_local];
    ull acc[4];
    #pragma unroll
    for (int j = 0; j < 4; j++) acc[j] = pk(bb, bb);
    #pragma unroll 4
    for (int d = 0; d < K; d++) {
        ull Wp = pk(swt[d*65 + e_local], swt[d*65 + e_local]);
        const ull* tp = (const ull*)&sxT[d*40 + tg*8];
        fma2(acc[0], Wp, tp[0]);
        fma2(acc[1], Wp, tp[1]);
        fma2(acc[2], Wp, tp[2]);
        fma2(acc[3], Wp, tp[3]);
    }
    #pragma unroll
    for (int j = 0; j < 4; j++) {
        float2 y = upk(acc[j]);
        if (actGelu) { y.x = gelu_f(y.x); y.y = gelu_f(y.y); }
        Y[(row0 + tg*8 + 2*j  )*N + e0 + e_local] = y.x;
        Y[(row0 + tg*8 + 2*j+1)*N + e0 + e_local] = y.y;
    }
}

/* ============================================================
   Kernel 3: GEMM (N=128) + residual + LayerNorm epilogue, f32x2
   ============================================================ */
__global__ __launch_bounds__(256) void gemm_ln_kernel(
    const float* __restrict__ X, const float* __restrict__ W,
    const float* __restrict__ bias,
    const float* __restrict__ Res,
    const float* __restrict__ lng, const float* __restrict__ lnb,
    float* __restrict__ Out, int K)
{
    extern __shared__ float sm[];
    float* sxT = sm;               /* [K][40]  */
    float* swt = sm + K*40;        /* [K][65]  */
    float* sy  = swt + K*65;       /* [32][132] */
    const int row0 = blockIdx.x*32;
    const int tid  = threadIdx.x;

    for (int li = tid; li < 32*K; li += 256) {
        int r = li / K, d = li - r*K;
        sxT[d*40 + r] = X[(row0+r)*K + d];
    }
    const int e_local = tid & 63, tg = tid >> 6;

    for (int e0 = 0; e0 < 128; e0 += 64) {
        __syncthreads();
        for (int li = tid; li < 64*K; li += 256) {
            int e = li / K, d = li - e*K;
            swt[d*65 + e] = W[(e0+e)*K + d];
        }
        __syncthreads();
        float bb = bias[e0 + e_local];
        ull acc[4];
        #pragma unroll
        for (int j = 0; j < 4; j++) acc[j] = pk(bb, bb);
        #pragma unroll 4
        for (int d = 0; d < K; d++) {
            ull Wp = pk(swt[d*65 + e_local], swt[d*65 + e_local]);
            const ull* tp = (const ull*)&sxT[d*40 + tg*8];
            fma2(acc[0], Wp, tp[0]);
            fma2(acc[1], Wp, tp[1]);
            fma2(acc[2], Wp, tp[2]);
            fma2(acc[3], Wp, tp[3]);
        }
        #pragma unroll
        for (int j = 0; j < 4; j++) {
            float2 y = upk(acc[j]);
            sy[(tg*8 + 2*j  )*132 + e0 + e_local] = y.x;
            sy[(tg*8 + 2*j+1)*132 + e0 + e_local] = y.y;
        }
    }
    __syncthreads();

    const int w = tid >> 5, lane = tid & 31;
    for (int q = 0; q < 4; q++) {
        int r = w*4 + q;
        float z[4]; float s1 = 0.f, s2 = 0.f;
        #pragma unroll
        for (int i = 0; i < 4; i++) {
            int idx = lane + 32*i;
            float zz = sy[r*132 + idx] + Res[(row0+r)*128 + idx];
            z[i] = zz; s1 += zz; s2 += zz*zz;
        }
        #pragma unroll
        for (int o = 16; o > 0; o >>= 1) {
            s1 += __shfl_xor_sync(0xffffffffu, s1, o);
            s2 += __shfl_xor_sync(0xffffffffu, s2, o);
        }
        float mean = s1*(1.f/128.f);
        float var  = s2*(1.f/128.f) - mean*mean;
        float rs   = rsqrtf(var + EPSf);
        #pragma unroll
        for (int i = 0; i < 4; i++) {
            int idx = lane + 32*i;
            Out[(row0+r)*128 + idx] = (z[i]-mean)*rs*lng[idx] + lnb[idx];
        }
    }
}

/* ============================================================
   Kernel 4: attention per (b, head). seq=122, dh=16.
   ============================================================ */
__global__ __launch_bounds__(128) void attn_kernel(
    const float* __restrict__ qkv, float* __restrict__ ctx)
{
    const int b = blockIdx.x >> 3, h = blockIdx.x & 7;
    extern __shared__ float sm[];
    float* sq = sm;                 /* [122][17] */
    float* sk = sm + 122*17;
    float* sv = sm + 2*122*17;
    float* sattb = sm + 3*122*17;   /* [4][128] */
    const int tid = threadIdx.x;

    for (int li = tid; li < 122*16; li += 128) {
        int s = li >> 4, d = li & 15;
        int base = (b*Cn + s)*384 + h*16 + d;
        sq[s*17 + d] = qkv[base];
        sk[s*17 + d] = qkv[base + 128];
        sv[s*17 + d] = qkv[base + 256];
    }
    __syncthreads();

    const int w = tid >> 5, lane = tid & 31;
    float* satt = sattb + w*128;

    for (int i = w; i < Cn; i += 4) {
        float sc[4];
        #pragma unroll
        for (int c = 0; c < 4; c++) {
            int kk = lane + 32*c;
            if (kk < Cn) {
                float s = 0.f;
                #pragma unroll
                for (int d = 0; d < 16; d++) s += sq[i*17 + d]*sk[kk*17 + d];
                sc[c] = s*0.25f;
            } else sc[c] = -1e30f;
        }
        float mx = fmaxf(fmaxf(sc[0], sc[1]), fmaxf(sc[2], sc[3]));
        #pragma unroll
        for (int o = 16; o > 0; o >>= 1) mx = fmaxf(mx, __shfl_xor_sync(0xffffffffu, mx, o));
        float p[4]; float sum = 0.f;
        #pragma unroll
        for (int c = 0; c < 4; c++) {
            int kk = lane + 32*c;
            p[c] = (kk < Cn) ? expf(sc[c]-mx) : 0.f;
            sum += p[c];
        }
        #pragma unroll
        for (int o = 16; o > 0; o >>= 1) sum += __shfl_xor_sync(0xffffffffu, sum, o);
        float inv = 1.f/sum;
        #pragma unroll
        for (int c = 0; c < 4; c++) {
            int kk = lane + 32*c;
            if (kk < Cn) satt[kk] = p[c]*inv;
        }
        __syncwarp();
        int d = lane & 15, half = lane >> 4;
        float a = 0.f;
        int j0 = half*61;
        for (int j = j0; j < j0 + 61; j++) a += satt[j]*sv[j*17 + d];
        a += __shfl_xor_sync(0xffffffffu, a, 16);
        if (lane < 16) ctx[(b*Cn + i)*Dn + h*16 + d] = a;
        __syncwarp();
    }
}

/* ============================================================
   Kernel 5: mean over C + per-subject head -> out[64,4]
   ============================================================ */
__global__ __launch_bounds__(128) void head_kernel(
    const float* __restrict__ tok, const int* __restrict__ sid,
    const float* __restrict__ hw, const float* __restrict__ hb,
    float* __restrict__ out)
{
    const int b = blockIdx.x;
    __shared__ float sp[128];
    const int d = threadIdx.x;
    float s = 0.f;
    for (int c = 0; c < Cn; c++) s += tok[(b*Cn + c)*Dn + d];
    sp[d] = s*(1.f/(float)Cn);
    __syncthreads();
    const int cls = threadIdx.x >> 5, lane = threadIdx.x & 31;
    const int sb = sid[b];
    float a = 0.f;
    #pragma unroll
    for (int i = 0; i < 4; i++) {
        int dd = lane + 32*i;
        a += sp[dd]*hw[(sb*4 + cls)*Dn + dd];
    }
    #pragma unroll
    for (int o = 16; o > 0; o >>= 1) a += __shfl_xor_sync(0xffffffffu, a, o);
    if (lane == 0) out[b*4 + cls] = a + hb[sb*4 + cls];
}

/* ============================================================ */
extern "C" void kernel_launch(void* const* d_in, const int* in_sizes, int n_in,
                              void* d_out, int out_size)
{
    const float* x       = (const float*)d_in[0];
    const int*   sid     = (const int*  )d_in[1];
    const float* conv1_w = (const float*)d_in[2];
    const float* conv1_b = (const float*)d_in[3];
    const float* bn1_g   = (const float*)d_in[4];
    const float* bn1_b   = (const float*)d_in[5];
    const float* bn1_m   = (const float*)d_in[6];
    const float* bn1_v   = (const float*)d_in[7];
    const float* conv2_w = (const float*)d_in[8];
    const float* conv2_b = (const float*)d_in[9];
    const float* bn2_g   = (const float*)d_in[10];
    const float* bn2_b   = (const float*)d_in[11];
    const float* bn2_m   = (const float*)d_in[12];
    const float* bn2_v   = (const float*)d_in[13];
    const float* proj_w  = (const float*)d_in[14];
    const float* proj_b  = (const float*)d_in[15];
    const float* emb     = (const float*)d_in[16];
    const float* qkv_w   = (const float*)d_in[17];
    const float* qkv_b   = (const float*)d_in[18];
    const float* out_w   = (const float*)d_in[19];
    const float* out_b   = (const float*)d_in[20];
    const float* ln1_g   = (const float*)d_in[21];
    const float* ln1_b   = (const float*)d_in[22];
    const float* ff1_w   = (const float*)d_in[23];
    const float* ff1_b   = (const float*)d_in[24];
    const float* ff2_w   = (const float*)d_in[25];
    const float* ff2_b   = (const float*)d_in[26];
    const float* ln2_g   = (const float*)d_in[27];
    const float* ln2_b   = (const float*)d_in[28];
    const float* heads_w = (const float*)d_in[29];
    const float* heads_b = (const float*)d_in[30];

    const int CONV_SMEM   = 226816;                        /* bytes */
    const int GEMM_SMEM   = (128*40 + 128*65)*4;           /* 53760 B  */
    const int GLN_SMEM128 = (128*40 + 128*65 + 32*132)*4;  /* 70656 B  */
    const int GLN_SMEM256 = (256*40 + 256*65 + 32*132)*4;  /* 124416 B */
    const int ATTN_SMEM   = (3*122*17 + 4*128)*4;          /* 26936 B  */

    cudaFuncSetAttribute(conv_kernel,    cudaFuncAttributeMaxDynamicSharedMemorySize, CONV_SMEM);
    cudaFuncSetAttribute(gemm_kernel,    cudaFuncAttributeMaxDynamicSharedMemorySize, GEMM_SMEM);
    cudaFuncSetAttribute(gemm_ln_kernel, cudaFuncAttributeMaxDynamicSharedMemorySize, GLN_SMEM256);

    float* tokp = nullptr; float* qkvp = nullptr; float* ctxp = nullptr; float* ffp = nullptr;
    cudaGetSymbolAddress((void**)&tokp, g_tok);
    cudaGetSymbolAddress((void**)&qkvp, g_qkv);
    cudaGetSymbolAddress((void**)&ctxp, g_ctx);
    cudaGetSymbolAddress((void**)&ffp,  g_ff);

    conv_kernel<<<BC, 512, CONV_SMEM>>>(
        x, conv1_w, conv1_b, bn1_g, bn1_b, bn1_m, bn1_v,
        conv2_w, conv2_b, bn2_g, bn2_b, bn2_m, bn2_v,
        proj_w, proj_b, emb, tokp);

    for (int l = 0; l < Lln; l++) {
        gemm_kernel<<<dim3(244, 6), 256, GEMM_SMEM>>>(
            tokp, qkv_w + l*3*Dn*Dn, qkv_b + l*3*Dn, qkvp, Dn, 3*Dn, 0);
        attn_kernel<<<Bn*Hn, 128, ATTN_SMEM>>>(qkvp, ctxp);
        gemm_ln_kernel<<<244, 256, GLN_SMEM128>>>(
            ctxp, out_w + l*Dn*Dn, out_b + l*Dn,
            tokp, ln1_g + l*Dn, ln1_b + l*Dn, tokp, Dn);
        gemm_kernel<<<dim3(244, 4), 256, GEMM_SMEM>>>(
            tokp, ff1_w + l*FFn*Dn, ff1_b + l*FFn, ffp, Dn, FFn, 1);
        gemm_ln_kernel<<<244, 256, GLN_SMEM256>>>(
            ffp, ff2_w + l*Dn*FFn, ff2_b + l*Dn,
            tokp, ln2_g + l*Dn, ln2_b + l*Dn, tokp, FFn);
    }

    head_kernel<<<Bn, 128>>>(tokp, sid, heads_w, heads_b, (float*)d_out);
}

// round 6
// speedup vs baseline: 1.4204x; 1.1107x over previous
#include <cuda_runtime.h>

#define Bn   64
#define Cn   122
#define Tn   500
#define COn  64
#define Dn   128
#define Hn   8
#define FFn  256
#define Lln  2
#define BC   (Bn*Cn)        /* 7808 = 244*32 */
#define EPSf 1e-5f

typedef unsigned long long ull;
typedef unsigned int uint32;

/* ---------------- scratch (device globals; no allocation) ---------------- */
__device__ float g_tok[BC*Dn];
__device__ float g_qkv[BC*3*Dn];
__device__ float g_ctx[BC*Dn];
__device__ float g_ff [BC*FFn];

__device__ __forceinline__ float gelu_f(float x){
    return 0.5f*x*(1.0f + erff(x*0.70710678118654752440f));
}

/* packed f32x2 helpers (transformer GEMMs) */
__device__ __forceinline__ ull pk(float a, float b){
    ull r; asm("mov.b64 %0, {%1, %2};" : "=l"(r) : "f"(a), "f"(b)); return r;
}
__device__ __forceinline__ void fma2(ull& d, ull a, ull b){
    asm("fma.rn.f32x2 %0, %1, %2, %0;" : "+l"(d) : "l"(a), "l"(b));
}
__device__ __forceinline__ float2 upk(ull a){
    float2 f; asm("mov.b64 {%0, %1}, %2;" : "=f"(f.x), "=f"(f.y) : "l"(a)); return f;
}

__device__ __forceinline__ uint32 tf32_rna(float v){
    uint32 u; asm("cvt.rna.tf32.f32 %0, %1;" : "=r"(u) : "f"(v)); return u;
}
__device__ __forceinline__ float tf32_hi(float v){
    return __uint_as_float(tf32_rna(v));
}
__device__ __forceinline__ void mma_tf32(float* c,
    uint32 a0, uint32 a1, uint32 a2, uint32 a3, uint32 b0, uint32 b1){
    asm volatile("mma.sync.aligned.m16n8k8.row.col.f32.tf32.tf32.f32 "
        "{%0,%1,%2,%3}, {%4,%5,%6,%7}, {%8,%9}, {%0,%1,%2,%3};"
        : "+f"(c[0]), "+f"(c[1]), "+f"(c[2]), "+f"(c[3])
        : "r"(a0), "r"(a1), "r"(a2), "r"(a3), "r"(b0), "r"(b1));
}

/* ============================================================
   Kernel 1: per-(b,c) fused conv pipeline, 512 threads.
   conv2 on tensor cores with 3xTF32 compensation:
     D = Wh*ah + Wh*al + Wl*ah  (drop Wl*al ~ 2^-22)
   C[64co, 256t] = W'[64, 320] x B[320, 256], k' = kk*64 + ci,
   B[k'][n] = h1[ci][n + kk - 2]  (conv pad 2; spair data at col 2+tp,
   reads use col = n + kk  ->  tp = n + kk - 2).
   SMEM (bytes):
     spH    @0       uint2[32*276]  act hi (ci & ci+4 paired)  70656
     spL    @70656   uint2[32*276]  act lo                     70656
     apair  @141312  uint2[64*164]  weights (k & k+4 paired),
                     holds HI in phase1, reloaded with LO      83968
     sx     @225280  float[512]
     sw1    @227328  float[576]
     sA1/B1/A2/B2 @229632 float[256]
     spart  @230656  float[64]
     sh2    @230912  float[64]     total 231168 B
   ============================================================ */
__global__ __launch_bounds__(512) void conv_kernel(
    const float* __restrict__ x,
    const float* __restrict__ w1, const float* __restrict__ cb1,
    const float* __restrict__ g1, const float* __restrict__ be1,
    const float* __restrict__ m1, const float* __restrict__ v1,
    const float* __restrict__ w2, const float* __restrict__ cb2,
    const float* __restrict__ g2, const float* __restrict__ be2,
    const float* __restrict__ m2, const float* __restrict__ v2,
    const float* __restrict__ pw, const float* __restrict__ pb,
    const float* __restrict__ emb, float* __restrict__ tok)
{
    extern __shared__ char smraw[];
    uint2* spH   = (uint2*)(smraw);
    uint2* spL   = (uint2*)(smraw + 70656);
    uint2* apair = (uint2*)(smraw + 141312);
    float* sx    = (float*)(smraw + 225280);
    float* sw1   = (float*)(smraw + 227328);
    float* sA1   = (float*)(smraw + 229632);
    float* sB1   = sA1 + 64;
    float* sA2   = sA1 + 128;
    float* sB2   = sA1 + 192;
    float* spart = (float*)(smraw + 230656);
    float* sh2   = (float*)(smraw + 230912);

    const int bc  = blockIdx.x;
    const int tid = threadIdx.x;

    /* ---- phase 0: loads / hi-weight conversion / zeroing ---- */
    {
        int t = tid - 4;
        sx[tid] = (t >= 0 && t < Tn) ? x[bc*Tn + t] : 0.f;
    }
    for (int i = tid; i < COn*9; i += 512) sw1[i] = w1[i];
    if (tid < 64) {
        float a1 = g1[tid]*rsqrtf(v1[tid]+EPSf);
        sA1[tid] = a1;  sB1[tid] = (cb1[tid]-m1[tid])*a1 + be1[tid];
        float a2 = g2[tid]*rsqrtf(v2[tid]+EPSf);
        sA2[tid] = a2;  sB2[tid] = (cb2[tid]-m2[tid])*a2 + be2[tid];
        spart[tid] = 0.f;
    }
    /* HI weights -> apair[co][q]; q = (k>>3)*4 + (k&3), khi = klo+4
       W'[co][kk*64+ci] = w2[co*320+ci*5+kk] */
    for (int i = tid; i < COn*160; i += 512) {
        int co = i / 160, q = i - co*160;
        int chunk = q >> 2, c = q & 3;
        int klo = chunk*8 + c;
        int kk = klo >> 6, ci = klo & 63;
        uint32 lo = tf32_rna(w2[co*320 + ci*5 + kk]);
        uint32 hi = tf32_rna(w2[co*320 + (ci+4)*5 + kk]);
        apair[co*164 + q] = make_uint2(lo, hi);
    }
    /* zero pad cols {0,1} U [252,262) in both act arrays */
    for (int i = tid; i < 32*12; i += 512) {
        int row = i / 12, j = i - row*12;
        int col = (j < 2) ? j : (250 + j);
        spH[row*276 + col] = make_uint2(0u, 0u);
        spL[row*276 + col] = make_uint2(0u, 0u);
    }
    __syncthreads();

    /* ---- conv1 + BN + GELU + maxpool(2) -> spH/spL (tf32 split) ---- */
    for (int i = tid; i < COn*250; i += 512) {
        int co = i / 250; int tp = i - co*250;
        const float* wp = &sw1[co*9];
        const float* xp = &sx[2*tp];
        float a0 = 0.f, a1 = 0.f;
        #pragma unroll
        for (int k = 0; k < 9; k++) { a0 += xp[k]*wp[k]; a1 += xp[k+1]*wp[k]; }
        float A = sA1[co], Bv = sB1[co];
        float y0 = gelu_f(a0*A + Bv);
        float y1 = gelu_f(a1*A + Bv);
        float m  = fmaxf(y0, y1);
        float mh = tf32_hi(m);
        float ml = m - mh;
        int P   = (co >> 3)*4 + (co & 3);
        int sel = (co >> 2) & 1;
        ((uint32*)&spH[P*276 + 2 + tp])[sel] = __float_as_uint(mh);
        ((uint32*)&spL[P*276 + 2 + tp])[sel] = tf32_rna(ml);
    }
    __syncthreads();

    /* ---- conv2 via tensor cores, 3xTF32 ----
       warp w: mchunk = w&1 (32 co), nchunk = w>>1 (32 t).
       NOTE: ncol0 base 0 (not 2): col = n + kk  -> tp = n + kk - 2. */
    {
        const int wid = tid >> 5, lane = tid & 31;
        const int mchunk = wid & 1, nchunk = wid >> 1;
        const int g = lane >> 2, t4 = lane & 3;

        float acc[2][4][4];
        #pragma unroll
        for (int mi = 0; mi < 2; mi++)
            #pragma unroll
            for (int nj = 0; nj < 4; nj++)
                #pragma unroll
                for (int r = 0; r < 4; r++) acc[mi][nj][r] = 0.f;

        const int ncol0 = nchunk*32 + g;   /* FIXED: was 2 + nchunk*32 + g */
        const int arow[2] = { (mchunk*32 + g)*164 + t4,
                              (mchunk*32 + 16 + g)*164 + t4 };

        /* ---- phase 1: Wh*ah + Wh*al ---- */
        {
            const uint2* ap[2][2];
            #pragma unroll
            for (int mi = 0; mi < 2; mi++) {
                ap[mi][0] = &apair[arow[mi]];
                ap[mi][1] = &apair[arow[mi] + 8*164];
            }
            #pragma unroll
            for (int kk = 0; kk < 5; kk++) {
                #pragma unroll
                for (int s = 0; s < 8; s++) {
                    uint2 aLo[2], aHi[2];
                    #pragma unroll
                    for (int mi = 0; mi < 2; mi++) {
                        aLo[mi] = *ap[mi][0];  ap[mi][0] += 4;
                        aHi[mi] = *ap[mi][1];  ap[mi][1] += 4;
                    }
                    const int boff = (s*4 + t4)*276 + ncol0 + kk;
                    #pragma unroll
                    for (int nj = 0; nj < 4; nj++) {
                        uint2 bh = spH[boff + nj*8];
                        uint2 bl = spL[boff + nj*8];
                        #pragma unroll
                        for (int mi = 0; mi < 2; mi++) {
                            mma_tf32(acc[mi][nj],
                                     aLo[mi].x, aHi[mi].x, aLo[mi].y, aHi[mi].y,
                                     bh.x, bh.y);
                            mma_tf32(acc[mi][nj],
                                     aLo[mi].x, aHi[mi].x, aLo[mi].y, aHi[mi].y,
                                     bl.x, bl.y);
                        }
                    }
                }
            }
        }
        __syncthreads();
        /* reload apair with LO weights */
        for (int i = tid; i < COn*160; i += 512) {
            int co = i / 160, q = i - co*160;
            int chunk = q >> 2, c = q & 3;
            int klo = chunk*8 + c;
            int kk = klo >> 6, ci = klo & 63;
            float w0 = w2[co*320 + ci*5 + kk];
            float w4 = w2[co*320 + (ci+4)*5 + kk];
            uint32 lo = tf32_rna(w0 - tf32_hi(w0));
            uint32 hi = tf32_rna(w4 - tf32_hi(w4));
            apair[co*164 + q] = make_uint2(lo, hi);
        }
        __syncthreads();

        /* ---- phase 2: Wl*ah ---- */
        {
            const uint2* ap[2][2];
            #pragma unroll
            for (int mi = 0; mi < 2; mi++) {
                ap[mi][0] = &apair[arow[mi]];
                ap[mi][1] = &apair[arow[mi] + 8*164];
            }
            #pragma unroll
            for (int kk = 0; kk < 5; kk++) {
                #pragma unroll
                for (int s = 0; s < 8; s++) {
                    uint2 aLo[2], aHi[2];
                    #pragma unroll
                    for (int mi = 0; mi < 2; mi++) {
                        aLo[mi] = *ap[mi][0];  ap[mi][0] += 4;
                        aHi[mi] = *ap[mi][1];  ap[mi][1] += 4;
                    }
                    const int boff = (s*4 + t4)*276 + ncol0 + kk;
                    #pragma unroll
                    for (int nj = 0; nj < 4; nj++) {
                        uint2 bh = spH[boff + nj*8];
                        #pragma unroll
                        for (int mi = 0; mi < 2; mi++)
                            mma_tf32(acc[mi][nj],
                                     aLo[mi].x, aHi[mi].x, aLo[mi].y, aHi[mi].y,
                                     bh.x, bh.y);
                    }
                }
            }
        }

        /* epilogue: BN + GELU + partial mean over t */
        #pragma unroll
        for (int mi = 0; mi < 2; mi++) {
            #pragma unroll
            for (int h = 0; h < 2; h++) {
                int r = mchunk*32 + mi*16 + g + h*8;
                float A = sA2[r], Bv = sB2[r];
                float rs = 0.f;
                #pragma unroll
                for (int nj = 0; nj < 4; nj++) {
                    #pragma unroll
                    for (int p = 0; p < 2; p++) {
                        int col = nchunk*32 + nj*8 + 2*t4 + p;
                        if (col < 250)
                            rs += gelu_f(acc[mi][nj][h*2+p]*A + Bv);
                    }
                }
                rs += __shfl_xor_sync(0xffffffffu, rs, 1);
                rs += __shfl_xor_sync(0xffffffffu, rs, 2);
                if (t4 == 0) atomicAdd(&spart[r], rs);
            }
        }
    }
    __syncthreads();
    if (tid < 64) sh2[tid] = spart[tid] * (1.f/250.f);
    __syncthreads();

    /* proj + elec_emb -> tok */
    if (tid < 128) {
        const int d = tid;
        float acc = pb[d];
        const float* pwr = &pw[d*COn];
        #pragma unroll 8
        for (int c = 0; c < 64; c++) acc += sh2[c]*__ldg(&pwr[c]);
        int cidx = bc % Cn;
        tok[bc*Dn + d] = acc + emb[cidx*Dn + d];
    }
}

/* ============================================================
   Kernel 2: tiled GEMM  Y[M,N] = act(X[M,K] @ W[N,K]^T + bias)
   ============================================================ */
__global__ __launch_bounds__(256) void gemm_kernel(
    const float* __restrict__ X, const float* __restrict__ W,
    const float* __restrict__ bias, float* __restrict__ Y,
    int K, int N, int actGelu)
{
    extern __shared__ float sm[];
    float* sxT = sm;            /* [K][40] */
    float* swt = sm + K*40;     /* [K][65] */
    const int row0 = blockIdx.x*32;
    const int e0   = blockIdx.y*64;
    const int tid  = threadIdx.x;

    for (int li = tid; li < 32*K; li += 256) {
        int r = li / K, d = li - r*K;
        sxT[d*40 + r] = X[(row0+r)*K + d];
    }
    for (int li = tid; li < 64*K; li += 256) {
        int e = li / K, d = li - e*K;
        swt[d*65 + e] = W[(e0+e)*K + d];
    }
    __syncthreads();

    const int e_local = tid & 63, tg = tid >> 6;
    float bb = bias[e0 + e_local];
    ull acc[4];
    #pragma unroll
    for (int j = 0; j < 4; j++) acc[j] = pk(bb, bb);
    #pragma unroll 4
    for (int d = 0; d < K; d++) {
        ull Wp = pk(swt[d*65 + e_local], swt[d*65 + e_local]);
        const ull* tp = (const ull*)&sxT[d*40 + tg*8];
        fma2(acc[0], Wp, tp[0]);
        fma2(acc[1], Wp, tp[1]);
        fma2(acc[2], Wp, tp[2]);
        fma2(acc[3], Wp, tp[3]);
    }
    #pragma unroll
    for (int j = 0; j < 4; j++) {
        float2 y = upk(acc[j]);
        if (actGelu) { y.x = gelu_f(y.x); y.y = gelu_f(y.y); }
        Y[(row0 + tg*8 + 2*j  )*N + e0 + e_local] = y.x;
        Y[(row0 + tg*8 + 2*j+1)*N + e0 + e_local] = y.y;
    }
}

/* ============================================================
   Kernel 3: GEMM (N=128) + residual + LayerNorm epilogue
   ============================================================ */
__global__ __launch_bounds__(256) void gemm_ln_kernel(
    const float* __restrict__ X, const float* __restrict__ W,
    const float* __restrict__ bias,
    const float* __restrict__ Res,
    const float* __restrict__ lng, const float* __restrict__ lnb,
    float* __restrict__ Out, int K)
{
    extern __shared__ float sm[];
    float* sxT = sm;               /* [K][40]  */
    float* swt = sm + K*40;        /* [K][65]  */
    float* sy  = swt + K*65;       /* [32][132] */
    const int row0 = blockIdx.x*32;
    const int tid  = threadIdx.x;

    for (int li = tid; li < 32*K; li += 256) {
        int r = li / K, d = li - r*K;
        sxT[d*40 + r] = X[(row0+r)*K + d];
    }
    const int e_local = tid & 63, tg = tid >> 6;

    for (int e0 = 0; e0 < 128; e0 += 64) {
        __syncthreads();
        for (int li = tid; li < 64*K; li += 256) {
            int e = li / K, d = li - e*K;
            swt[d*65 + e] = W[(e0+e)*K + d];
        }
        __syncthreads();
        float bb = bias[e0 + e_local];
        ull acc[4];
        #pragma unroll
        for (int j = 0; j < 4; j++) acc[j] = pk(bb, bb);
        #pragma unroll 4
        for (int d = 0; d < K; d++) {
            ull Wp = pk(swt[d*65 + e_local], swt[d*65 + e_local]);
            const ull* tp = (const ull*)&sxT[d*40 + tg*8];
            fma2(acc[0], Wp, tp[0]);
            fma2(acc[1], Wp, tp[1]);
            fma2(acc[2], Wp, tp[2]);
            fma2(acc[3], Wp, tp[3]);
        }
        #pragma unroll
        for (int j = 0; j < 4; j++) {
            float2 y = upk(acc[j]);
            sy[(tg*8 + 2*j  )*132 + e0 + e_local] = y.x;
            sy[(tg*8 + 2*j+1)*132 + e0 + e_local] = y.y;
        }
    }
    __syncthreads();

    const int w = tid >> 5, lane = tid & 31;
    for (int q = 0; q < 4; q++) {
        int r = w*4 + q;
        float z[4]; float s1 = 0.f, s2 = 0.f;
        #pragma unroll
        for (int i = 0; i < 4; i++) {
            int idx = lane + 32*i;
            float zz = sy[r*132 + idx] + Res[(row0+r)*128 + idx];
            z[i] = zz; s1 += zz; s2 += zz*zz;
        }
        #pragma unroll
        for (int o = 16; o > 0; o >>= 1) {
            s1 += __shfl_xor_sync(0xffffffffu, s1, o);
            s2 += __shfl_xor_sync(0xffffffffu, s2, o);
        }
        float mean = s1*(1.f/128.f);
        float var  = s2*(1.f/128.f) - mean*mean;
        float rs   = rsqrtf(var + EPSf);
        #pragma unroll
        for (int i = 0; i < 4; i++) {
            int idx = lane + 32*i;
            Out[(row0+r)*128 + idx] = (z[i]-mean)*rs*lng[idx] + lnb[idx];
        }
    }
}

/* ============================================================
   Kernel 4: attention per (b, head). seq=122, dh=16.
   ============================================================ */
__global__ __launch_bounds__(128) void attn_kernel(
    const float* __restrict__ qkv, float* __restrict__ ctx)
{
    const int b = blockIdx.x >> 3, h = blockIdx.x & 7;
    extern __shared__ float sm[];
    float* sq = sm;                 /* [122][17] */
    float* sk = sm + 122*17;
    float* sv = sm + 2*122*17;
    float* sattb = sm + 3*122*17;   /* [4][128] */
    const int tid = threadIdx.x;

    for (int li = tid; li < 122*16; li += 128) {
        int s = li >> 4, d = li & 15;
        int base = (b*Cn + s)*384 + h*16 + d;
        sq[s*17 + d] = qkv[base];
        sk[s*17 + d] = qkv[base + 128];
        sv[s*17 + d] = qkv[base + 256];
    }
    __syncthreads();

    const int w = tid >> 5, lane = tid & 31;
    float* satt = sattb + w*128;

    for (int i = w; i < Cn; i += 4) {
        float sc[4];
        #pragma unroll
        for (int c = 0; c < 4; c++) {
            int kk = lane + 32*c;
            if (kk < Cn) {
                float s = 0.f;
                #pragma unroll
                for (int d = 0; d < 16; d++) s += sq[i*17 + d]*sk[kk*17 + d];
                sc[c] = s*0.25f;
            } else sc[c] = -1e30f;
        }
        float mx = fmaxf(fmaxf(sc[0], sc[1]), fmaxf(sc[2], sc[3]));
        #pragma unroll
        for (int o = 16; o > 0; o >>= 1) mx = fmaxf(mx, __shfl_xor_sync(0xffffffffu, mx, o));
        float p[4]; float sum = 0.f;
        #pragma unroll
        for (int c = 0; c < 4; c++) {
            int kk = lane + 32*c;
            p[c] = (kk < Cn) ? expf(sc[c]-mx) : 0.f;
            sum += p[c];
        }
        #pragma unroll
        for (int o = 16; o > 0; o >>= 1) sum += __shfl_xor_sync(0xffffffffu, sum, o);
        float inv = 1.f/sum;
        #pragma unroll
        for (int c = 0; c < 4; c++) {
            int kk = lane + 32*c;
            if (kk < Cn) satt[kk] = p[c]*inv;
        }
        __syncwarp();
        int d = lane & 15, half = lane >> 4;
        float a = 0.f;
        int j0 = half*61;
        for (int j = j0; j < j0 + 61; j++) a += satt[j]*sv[j*17 + d];
        a += __shfl_xor_sync(0xffffffffu, a, 16);
        if (lane < 16) ctx[(b*Cn + i)*Dn + h*16 + d] = a;
        __syncwarp();
    }
}

/* ============================================================
   Kernel 5: mean over C + per-subject head -> out[64,4]
   ============================================================ */
__global__ __launch_bounds__(128) void head_kernel(
    const float* __restrict__ tok, const int* __restrict__ sid,
    const float* __restrict__ hw, const float* __restrict__ hb,
    float* __restrict__ out)
{
    const int b = blockIdx.x;
    __shared__ float sp[128];
    const int d = threadIdx.x;
    float s = 0.f;
    for (int c = 0; c < Cn; c++) s += tok[(b*Cn + c)*Dn + d];
    sp[d] = s*(1.f/(float)Cn);
    __syncthreads();
    const int cls = threadIdx.x >> 5, lane = threadIdx.x & 31;
    const int sb = sid[b];
    float a = 0.f;
    #pragma unroll
    for (int i = 0; i < 4; i++) {
        int dd = lane + 32*i;
        a += sp[dd]*hw[(sb*4 + cls)*Dn + dd];
    }
    #pragma unroll
    for (int o = 16; o > 0; o >>= 1) a += __shfl_xor_sync(0xffffffffu, a, o);
    if (lane == 0) out[b*4 + cls] = a + hb[sb*4 + cls];
}

/* ============================================================ */
extern "C" void kernel_launch(void* const* d_in, const int* in_sizes, int n_in,
                              void* d_out, int out_size)
{
    const float* x       = (const float*)d_in[0];
    const int*   sid     = (const int*  )d_in[1];
    const float* conv1_w = (const float*)d_in[2];
    const float* conv1_b = (const float*)d_in[3];
    const float* bn1_g   = (const float*)d_in[4];
    const float* bn1_b   = (const float*)d_in[5];
    const float* bn1_m   = (const float*)d_in[6];
    const float* bn1_v   = (const float*)d_in[7];
    const float* conv2_w = (const float*)d_in[8];
    const float* conv2_b = (const float*)d_in[9];
    const float* bn2_g   = (const float*)d_in[10];
    const float* bn2_b   = (const float*)d_in[11];
    const float* bn2_m   = (const float*)d_in[12];
    const float* bn2_v   = (const float*)d_in[13];
    const float* proj_w  = (const float*)d_in[14];
    const float* proj_b  = (const float*)d_in[15];
    const float* emb     = (const float*)d_in[16];
    const float* qkv_w   = (const float*)d_in[17];
    const float* qkv_b   = (const float*)d_in[18];
    const float* out_w   = (const float*)d_in[19];
    const float* out_b   = (const float*)d_in[20];
    const float* ln1_g   = (const float*)d_in[21];
    const float* ln1_b   = (const float*)d_in[22];
    const float* ff1_w   = (const float*)d_in[23];
    const float* ff1_b   = (const float*)d_in[24];
    const float* ff2_w   = (const float*)d_in[25];
    const float* ff2_b   = (const float*)d_in[26];
    const float* ln2_g   = (const float*)d_in[27];
    const float* ln2_b   = (const float*)d_in[28];
    const float* heads_w = (const float*)d_in[29];
    const float* heads_b = (const float*)d_in[30];

    const int CONV_SMEM   = 231168;                        /* bytes */
    const int GEMM_SMEM   = (128*40 + 128*65)*4;           /* 53760 B  */
    const int GLN_SMEM128 = (128*40 + 128*65 + 32*132)*4;  /* 70656 B  */
    const int GLN_SMEM256 = (256*40 + 256*65 + 32*132)*4;  /* 124416 B */
    const int ATTN_SMEM   = (3*122*17 + 4*128)*4;          /* 26936 B  */

    cudaFuncSetAttribute(conv_kernel,    cudaFuncAttributeMaxDynamicSharedMemorySize, CONV_SMEM);
    cudaFuncSetAttribute(gemm_kernel,    cudaFuncAttributeMaxDynamicSharedMemorySize, GEMM_SMEM);
    cudaFuncSetAttribute(gemm_ln_kernel, cudaFuncAttributeMaxDynamicSharedMemorySize, GLN_SMEM256);

    float* tokp = nullptr; float* qkvp = nullptr; float* ctxp = nullptr; float* ffp = nullptr;
    cudaGetSymbolAddress((void**)&tokp, g_tok);
    cudaGetSymbolAddress((void**)&qkvp, g_qkv);
    cudaGetSymbolAddress((void**)&ctxp, g_ctx);
    cudaGetSymbolAddress((void**)&ffp,  g_ff);

    conv_kernel<<<BC, 512, CONV_SMEM>>>(
        x, conv1_w, conv1_b, bn1_g, bn1_b, bn1_m, bn1_v,
        conv2_w, conv2_b, bn2_g, bn2_b, bn2_m, bn2_v,
        proj_w, proj_b, emb, tokp);

    for (int l = 0; l < Lln; l++) {
        gemm_kernel<<<dim3(244, 6), 256, GEMM_SMEM>>>(
            tokp, qkv_w + l*3*Dn*Dn, qkv_b + l*3*Dn, qkvp, Dn, 3*Dn, 0);
        attn_kernel<<<Bn*Hn, 128, ATTN_SMEM>>>(qkvp, ctxp);
        gemm_ln_kernel<<<244, 256, GLN_SMEM128>>>(
            ctxp, out_w + l*Dn*Dn, out_b + l*Dn,
            tokp, ln1_g + l*Dn, ln1_b + l*Dn, tokp, Dn);
        gemm_kernel<<<dim3(244, 4), 256, GEMM_SMEM>>>(
            tokp, ff1_w + l*FFn*Dn, ff1_b + l*FFn, ffp, Dn, FFn, 1);
        gemm_ln_kernel<<<244, 256, GLN_SMEM256>>>(
            ffp, ff2_w + l*Dn*FFn, ff2_b + l*Dn,
            tokp, ln2_g + l*Dn, ln2_b + l*Dn, tokp, FFn);
    }

    head_kernel<<<Bn, 128>>>(tokp, sid, heads_w, heads_b, (float*)d_out);
}

// round 7
// speedup vs baseline: 2.0957x; 1.4754x over previous
#include <cuda_runtime.h>
#include <cuda_fp16.h>

#define Bn   64
#define Cn   122
#define Tn   500
#define COn  64
#define Dn   128
#define Hn   8
#define FFn  256
#define Lln  2
#define BC   (Bn*Cn)        /* 7808 = 244*32 */
#define EPSf 1e-5f

typedef unsigned long long ull;
typedef unsigned int uint32;

/* ---------------- scratch (device globals; no allocation) ---------------- */
__device__ float g_tok[BC*Dn];
__device__ float g_qkv[BC*3*Dn];
__device__ float g_ctx[BC*Dn];
__device__ float g_ff [BC*FFn];

__device__ __forceinline__ float gelu_f(float x){
    return 0.5f*x*(1.0f + erff(x*0.70710678118654752440f));
}

/* packed f32x2 helpers (transformer GEMMs) */
__device__ __forceinline__ ull pk(float a, float b){
    ull r; asm("mov.b64 %0, {%1, %2};" : "=l"(r) : "f"(a), "f"(b)); return r;
}
__device__ __forceinline__ void fma2(ull& d, ull a, ull b){
    asm("fma.rn.f32x2 %0, %1, %2, %0;" : "+l"(d) : "l"(a), "l"(b));
}
__device__ __forceinline__ float2 upk(ull a){
    float2 f; asm("mov.b64 {%0, %1}, %2;" : "=f"(f.x), "=f"(f.y) : "l"(a)); return f;
}

/* fp16 mma m16n8k16, fp32 accum */
__device__ __forceinline__ void mma_f16(float* c,
    uint32 a0, uint32 a1, uint32 a2, uint32 a3, uint32 b0, uint32 b1){
    asm volatile("mma.sync.aligned.m16n8k16.row.col.f32.f16.f16.f32 "
        "{%0,%1,%2,%3}, {%4,%5,%6,%7}, {%8,%9}, {%0,%1,%2,%3};"
        : "+f"(c[0]), "+f"(c[1]), "+f"(c[2]), "+f"(c[3])
        : "r"(a0), "r"(a1), "r"(a2), "r"(a3), "r"(b0), "r"(b1));
}

__device__ __forceinline__ uint32 h2pack(__half lo, __half hi){
    __half2 h = __halves2half2(lo, hi);
    return *(uint32*)&h;
}

/* ============================================================
   Kernel 1: per-(b,c) fused conv pipeline, 512 threads.
   conv2 on fp16 tensor cores (m16n8k16), 3-term split:
     D = Wh*ah + Wh*al + Wl*ah   (drop Wl*al ~ 2^-22)
   GEMM: C[64co, 256t] = W'[64,320] x B[320,256],
     k = kk*64 + ci, B[k][n] = h1[ci][n+kk-2] (pad 2).
   k split into 20 chunks of 16; chunk c16: kk = c16>>2,
     ci = (c16&3)*16 + j, j in [0,16).
   Activations: half2 pairs of ADJACENT channels (ci even):
     act[ci/2][col] = (h1[ci][col-2], h1[ci+1][col-2]), stride 264.
   Weights: half2 pairs of adjacent k:
     w[co][q] = (W'[co][2q], W'[co][2q+1]), stride 164.
   Bank check: B: bank = 8*t4 + g (all 32 distinct);
               A: bank = 4*g + t4 (all 32 distinct).
   SMEM (bytes):
     actH @0       uint32[32*264] 33792
     actL @33792   uint32[32*264] 33792
     wH   @67584   uint32[64*164] 41984
     wL   @109568  uint32[64*164] 41984
     sx   @151552  float[512]
     sw1  @153600  float[576]
     sA1/B1/A2/B2 @155904 float[256]
     spart@156928  float[64]
     sh2  @157184  float[64]   total 157440 B
   ============================================================ */
__global__ __launch_bounds__(512) void conv_kernel(
    const float* __restrict__ x,
    const float* __restrict__ w1, const float* __restrict__ cb1,
    const float* __restrict__ g1, const float* __restrict__ be1,
    const float* __restrict__ m1, const float* __restrict__ v1,
    const float* __restrict__ w2, const float* __restrict__ cb2,
    const float* __restrict__ g2, const float* __restrict__ be2,
    const float* __restrict__ m2, const float* __restrict__ v2,
    const float* __restrict__ pw, const float* __restrict__ pb,
    const float* __restrict__ emb, float* __restrict__ tok)
{
    extern __shared__ char smraw[];
    uint32* actH = (uint32*)(smraw);
    uint32* actL = (uint32*)(smraw + 33792);
    uint32* wH   = (uint32*)(smraw + 67584);
    uint32* wL   = (uint32*)(smraw + 109568);
    float* sx    = (float*)(smraw + 151552);
    float* sw1   = (float*)(smraw + 153600);
    float* sA1   = (float*)(smraw + 155904);
    float* sB1   = sA1 + 64;
    float* sA2   = sA1 + 128;
    float* sB2   = sA1 + 192;
    float* spart = (float*)(smraw + 156928);
    float* sh2   = (float*)(smraw + 157184);

    const int bc  = blockIdx.x;
    const int tid = threadIdx.x;

    /* ---- phase 0 ---- */
    {
        int t = tid - 4;
        sx[tid] = (t >= 0 && t < Tn) ? x[bc*Tn + t] : 0.f;
    }
    for (int i = tid; i < COn*9; i += 512) sw1[i] = w1[i];
    if (tid < 64) {
        float a1 = g1[tid]*rsqrtf(v1[tid]+EPSf);
        sA1[tid] = a1;  sB1[tid] = (cb1[tid]-m1[tid])*a1 + be1[tid];
        float a2 = g2[tid]*rsqrtf(v2[tid]+EPSf);
        sA2[tid] = a2;  sB2[tid] = (cb2[tid]-m2[tid])*a2 + be2[tid];
        spart[tid] = 0.f;
    }
    /* weights hi/lo -> wH/wL; pair (k=2q, k=2q+1): ci and ci+1 (same kk) */
    for (int i = tid; i < COn*160; i += 512) {
        int co = i / 160, q = i - co*160;
        int k0 = 2*q;
        int kk = k0 >> 6, ci = k0 & 63;
        float wa = w2[co*320 + ci*5 + kk];
        float wb = w2[co*320 + (ci+1)*5 + kk];
        __half wah = __float2half_rn(wa);
        __half wbh = __float2half_rn(wb);
        __half wal = __float2half_rn(wa - __half2float(wah));
        __half wbl = __float2half_rn(wb - __half2float(wbh));
        wH[co*164 + q] = h2pack(wah, wbh);
        wL[co*164 + q] = h2pack(wal, wbl);
    }
    /* zero pad cols {0,1} U [252,264) in both act arrays */
    for (int i = tid; i < 32*14; i += 512) {
        int row = i / 14, j = i - row*14;
        int col = (j < 2) ? j : (250 + j);
        actH[row*264 + col] = 0u;
        actL[row*264 + col] = 0u;
    }
    __syncthreads();

    /* ---- conv1 + BN + GELU + maxpool(2) -> actH/actL (fp16 split) ---- */
    for (int i = tid; i < COn*250; i += 512) {
        int co = i / 250; int tp = i - co*250;
        const float* wp = &sw1[co*9];
        const float* xp = &sx[2*tp];
        float a0 = 0.f, a1 = 0.f;
        #pragma unroll
        for (int k = 0; k < 9; k++) { a0 += xp[k]*wp[k]; a1 += xp[k+1]*wp[k]; }
        float A = sA1[co], Bv = sB1[co];
        float y0 = gelu_f(a0*A + Bv);
        float y1 = gelu_f(a1*A + Bv);
        float m  = fmaxf(y0, y1);
        __half mh = __float2half_rn(m);
        __half ml = __float2half_rn(m - __half2float(mh));
        int hidx = ((co >> 1)*264 + 2 + tp)*2 + (co & 1);
        ((__half*)actH)[hidx] = mh;
        ((__half*)actL)[hidx] = ml;
    }
    __syncthreads();

    /* ---- conv2 via fp16 tensor cores, single pass ----
       warp w: mchunk = w&1 (32 co), nchunk = w>>1 (32 t). */
    {
        const int wid = tid >> 5, lane = tid & 31;
        const int mchunk = wid & 1, nchunk = wid >> 1;
        const int g = lane >> 2, t4 = lane & 3;

        float acc[2][4][4];
        #pragma unroll
        for (int mi = 0; mi < 2; mi++)
            #pragma unroll
            for (int nj = 0; nj < 4; nj++)
                #pragma unroll
                for (int r = 0; r < 4; r++) acc[mi][nj][r] = 0.f;

        const int mrow0 = mchunk*32 + g;
        const int nbase = nchunk*32 + g;

        #pragma unroll 4
        for (int c16 = 0; c16 < 20; c16++) {
            const int kk = c16 >> 2;
            const int rb = ((c16 & 3)*8 + t4)*264;
            const int q0 = c16*8 + t4;

            uint32 aH[2][4], aL[2][4];
            #pragma unroll
            for (int mi = 0; mi < 2; mi++) {
                int r0 = (mrow0 + mi*16)*164 + q0;
                int r1 = r0 + 8*164;
                aH[mi][0] = wH[r0];     aH[mi][1] = wH[r1];
                aH[mi][2] = wH[r0 + 4]; aH[mi][3] = wH[r1 + 4];
                aL[mi][0] = wL[r0];     aL[mi][1] = wL[r1];
                aL[mi][2] = wL[r0 + 4]; aL[mi][3] = wL[r1 + 4];
            }
            #pragma unroll
            for (int nj = 0; nj < 4; nj++) {
                int cb = rb + nbase + nj*8 + kk;
                uint32 bh0 = actH[cb], bh1 = actH[cb + 4*264];
                uint32 bl0 = actL[cb], bl1 = actL[cb + 4*264];
                #pragma unroll
                for (int mi = 0; mi < 2; mi++) {
                    mma_f16(acc[mi][nj], aH[mi][0], aH[mi][1], aH[mi][2], aH[mi][3], bh0, bh1);
                    mma_f16(acc[mi][nj], aH[mi][0], aH[mi][1], aH[mi][2], aH[mi][3], bl0, bl1);
                    mma_f16(acc[mi][nj], aL[mi][0], aL[mi][1], aL[mi][2], aL[mi][3], bh0, bh1);
                }
            }
        }

        /* epilogue: BN + GELU + partial mean over t */
        #pragma unroll
        for (int mi = 0; mi < 2; mi++) {
            #pragma unroll
            for (int h = 0; h < 2; h++) {
                int r = mchunk*32 + mi*16 + g + h*8;
                float A = sA2[r], Bv = sB2[r];
                float rs = 0.f;
                #pragma unroll
                for (int nj = 0; nj < 4; nj++) {
                    #pragma unroll
                    for (int p = 0; p < 2; p++) {
                        int col = nchunk*32 + nj*8 + 2*t4 + p;
                        if (col < 250)
                            rs += gelu_f(acc[mi][nj][h*2+p]*A + Bv);
                    }
                }
                rs += __shfl_xor_sync(0xffffffffu, rs, 1);
                rs += __shfl_xor_sync(0xffffffffu, rs, 2);
                if (t4 == 0) atomicAdd(&spart[r], rs);
            }
        }
    }
    __syncthreads();
    if (tid < 64) sh2[tid] = spart[tid] * (1.f/250.f);
    __syncthreads();

    /* proj + elec_emb -> tok */
    if (tid < 128) {
        const int d = tid;
        float acc = pb[d];
        const float* pwr = &pw[d*COn];
        #pragma unroll 8
        for (int c = 0; c < 64; c++) acc += sh2[c]*__ldg(&pwr[c]);
        int cidx = bc % Cn;
        tok[bc*Dn + d] = acc + emb[cidx*Dn + d];
    }
}

/* ============================================================
   Kernel 2: tiled GEMM  Y[M,N] = act(X[M,K] @ W[N,K]^T + bias)
   ============================================================ */
__global__ __launch_bounds__(256) void gemm_kernel(
    const float* __restrict__ X, const float* __restrict__ W,
    const float* __restrict__ bias, float* __restrict__ Y,
    int K, int N, int actGelu)
{
    extern __shared__ float sm[];
    float* sxT = sm;            /* [K][40] */
    float* swt = sm + K*40;     /* [K][65] */
    const int row0 = blockIdx.x*32;
    const int e0   = blockIdx.y*64;
    const int tid  = threadIdx.x;

    for (int li = tid; li < 32*K; li += 256) {
        int r = li / K, d = li - r*K;
        sxT[d*40 + r] = X[(row0+r)*K + d];
    }
    for (int li = tid; li < 64*K; li += 256) {
        int e = li / K, d = li - e*K;
        swt[d*65 + e] = W[(e0+e)*K + d];
    }
    __syncthreads();

    const int e_local = tid & 63, tg = tid >> 6;
    float bb = bias[e0 + e_local];
    ull acc[4];
    #pragma unroll
    for (int j = 0; j < 4; j++) acc[j] = pk(bb, bb);
    #pragma unroll 4
    for (int d = 0; d < K; d++) {
        ull Wp = pk(swt[d*65 + e_local], swt[d*65 + e_local]);
        const ull* tp = (const ull*)&sxT[d*40 + tg*8];
        fma2(acc[0], Wp, tp[0]);
        fma2(acc[1], Wp, tp[1]);
        fma2(acc[2], Wp, tp[2]);
        fma2(acc[3], Wp, tp[3]);
    }
    #pragma unroll
    for (int j = 0; j < 4; j++) {
        float2 y = upk(acc[j]);
        if (actGelu) { y.x = gelu_f(y.x); y.y = gelu_f(y.y); }
        Y[(row0 + tg*8 + 2*j  )*N + e0 + e_local] = y.x;
        Y[(row0 + tg*8 + 2*j+1)*N + e0 + e_local] = y.y;
    }
}

/* ============================================================
   Kernel 3: GEMM (N=128) + residual + LayerNorm epilogue
   ============================================================ */
__global__ __launch_bounds__(256) void gemm_ln_kernel(
    const float* __restrict__ X, const float* __restrict__ W,
    const float* __restrict__ bias,
    const float* __restrict__ Res,
    const float* __restrict__ lng, const float* __restrict__ lnb,
    float* __restrict__ Out, int K)
{
    extern __shared__ float sm[];
    float* sxT = sm;               /* [K][40]  */
    float* swt = sm + K*40;        /* [K][65]  */
    float* sy  = swt + K*65;       /* [32][132] */
    const int row0 = blockIdx.x*32;
    const int tid  = threadIdx.x;

    for (int li = tid; li < 32*K; li += 256) {
        int r = li / K, d = li - r*K;
        sxT[d*40 + r] = X[(row0+r)*K + d];
    }
    const int e_local = tid & 63, tg = tid >> 6;

    for (int e0 = 0; e0 < 128; e0 += 64) {
        __syncthreads();
        for (int li = tid; li < 64*K; li += 256) {
            int e = li / K, d = li - e*K;
            swt[d*65 + e] = W[(e0+e)*K + d];
        }
        __syncthreads();
        float bb = bias[e0 + e_local];
        ull acc[4];
        #pragma unroll
        for (int j = 0; j < 4; j++) acc[j] = pk(bb, bb);
        #pragma unroll 4
        for (int d = 0; d < K; d++) {
            ull Wp = pk(swt[d*65 + e_local], swt[d*65 + e_local]);
            const ull* tp = (const ull*)&sxT[d*40 + tg*8];
            fma2(acc[0], Wp, tp[0]);
            fma2(acc[1], Wp, tp[1]);
            fma2(acc[2], Wp, tp[2]);
            fma2(acc[3], Wp, tp[3]);
        }
        #pragma unroll
        for (int j = 0; j < 4; j++) {
            float2 y = upk(acc[j]);
            sy[(tg*8 + 2*j  )*132 + e0 + e_local] = y.x;
            sy[(tg*8 + 2*j+1)*132 + e0 + e_local] = y.y;
        }
    }
    __syncthreads();

    const int w = tid >> 5, lane = tid & 31;
    for (int q = 0; q < 4; q++) {
        int r = w*4 + q;
        float z[4]; float s1 = 0.f, s2 = 0.f;
        #pragma unroll
        for (int i = 0; i < 4; i++) {
            int idx = lane + 32*i;
            float zz = sy[r*132 + idx] + Res[(row0+r)*128 + idx];
            z[i] = zz; s1 += zz; s2 += zz*zz;
        }
        #pragma unroll
        for (int o = 16; o > 0; o >>= 1) {
            s1 += __shfl_xor_sync(0xffffffffu, s1, o);
            s2 += __shfl_xor_sync(0xffffffffu, s2, o);
        }
        float mean = s1*(1.f/128.f);
        float var  = s2*(1.f/128.f) - mean*mean;
        float rs   = rsqrtf(var + EPSf);
        #pragma unroll
        for (int i = 0; i < 4; i++) {
            int idx = lane + 32*i;
            Out[(row0+r)*128 + idx] = (z[i]-mean)*rs*lng[idx] + lnb[idx];
        }
    }
}

/* ============================================================
   Kernel 4: attention per (b, head). seq=122, dh=16.
   ============================================================ */
__global__ __launch_bounds__(128) void attn_kernel(
    const float* __restrict__ qkv, float* __restrict__ ctx)
{
    const int b = blockIdx.x >> 3, h = blockIdx.x & 7;
    extern __shared__ float sm[];
    float* sq = sm;                 /* [122][17] */
    float* sk = sm + 122*17;
    float* sv = sm + 2*122*17;
    float* sattb = sm + 3*122*17;   /* [4][128] */
    const int tid = threadIdx.x;

    for (int li = tid; li < 122*16; li += 128) {
        int s = li >> 4, d = li & 15;
        int base = (b*Cn + s)*384 + h*16 + d;
        sq[s*17 + d] = qkv[base];
        sk[s*17 + d] = qkv[base + 128];
        sv[s*17 + d] = qkv[base + 256];
    }
    __syncthreads();

    const int w = tid >> 5, lane = tid & 31;
    float* satt = sattb + w*128;

    for (int i = w; i < Cn; i += 4) {
        float sc[4];
        #pragma unroll
        for (int c = 0; c < 4; c++) {
            int kk = lane + 32*c;
            if (kk < Cn) {
                float s = 0.f;
                #pragma unroll
                for (int d = 0; d < 16; d++) s += sq[i*17 + d]*sk[kk*17 + d];
                sc[c] = s*0.25f;
            } else sc[c] = -1e30f;
        }
        float mx = fmaxf(fmaxf(sc[0], sc[1]), fmaxf(sc[2], sc[3]));
        #pragma unroll
        for (int o = 16; o > 0; o >>= 1) mx = fmaxf(mx, __shfl_xor_sync(0xffffffffu, mx, o));
        float p[4]; float sum = 0.f;
        #pragma unroll
        for (int c = 0; c < 4; c++) {
            int kk = lane + 32*c;
            p[c] = (kk < Cn) ? expf(sc[c]-mx) : 0.f;
            sum += p[c];
        }
        #pragma unroll
        for (int o = 16; o > 0; o >>= 1) sum += __shfl_xor_sync(0xffffffffu, sum, o);
        float inv = 1.f/sum;
        #pragma unroll
        for (int c = 0; c < 4; c++) {
            int kk = lane + 32*c;
            if (kk < Cn) satt[kk] = p[c]*inv;
        }
        __syncwarp();
        int d = lane & 15, half = lane >> 4;
        float a = 0.f;
        int j0 = half*61;
        for (int j = j0; j < j0 + 61; j++) a += satt[j]*sv[j*17 + d];
        a += __shfl_xor_sync(0xffffffffu, a, 16);
        if (lane < 16) ctx[(b*Cn + i)*Dn + h*16 + d] = a;
        __syncwarp();
    }
}

/* ============================================================
   Kernel 5: mean over C + per-subject head -> out[64,4]
   ============================================================ */
__global__ __launch_bounds__(128) void head_kernel(
    const float* __restrict__ tok, const int* __restrict__ sid,
    const float* __restrict__ hw, const float* __restrict__ hb,
    float* __restrict__ out)
{
    const int b = blockIdx.x;
    __shared__ float sp[128];
    const int d = threadIdx.x;
    float s = 0.f;
    for (int c = 0; c < Cn; c++) s += tok[(b*Cn + c)*Dn + d];
    sp[d] = s*(1.f/(float)Cn);
    __syncthreads();
    const int cls = threadIdx.x >> 5, lane = threadIdx.x & 31;
    const int sb = sid[b];
    float a = 0.f;
    #pragma unroll
    for (int i = 0; i < 4; i++) {
        int dd = lane + 32*i;
        a += sp[dd]*hw[(sb*4 + cls)*Dn + dd];
    }
    #pragma unroll
    for (int o = 16; o > 0; o >>= 1) a += __shfl_xor_sync(0xffffffffu, a, o);
    if (lane == 0) out[b*4 + cls] = a + hb[sb*4 + cls];
}

/* ============================================================ */
extern "C" void kernel_launch(void* const* d_in, const int* in_sizes, int n_in,
                              void* d_out, int out_size)
{
    const float* x       = (const float*)d_in[0];
    const int*   sid     = (const int*  )d_in[1];
    const float* conv1_w = (const float*)d_in[2];
    const float* conv1_b = (const float*)d_in[3];
    const float* bn1_g   = (const float*)d_in[4];
    const float* bn1_b   = (const float*)d_in[5];
    const float* bn1_m   = (const float*)d_in[6];
    const float* bn1_v   = (const float*)d_in[7];
    const float* conv2_w = (const float*)d_in[8];
    const float* conv2_b = (const float*)d_in[9];
    const float* bn2_g   = (const float*)d_in[10];
    const float* bn2_b   = (const float*)d_in[11];
    const float* bn2_m   = (const float*)d_in[12];
    const float* bn2_v   = (const float*)d_in[13];
    const float* proj_w  = (const float*)d_in[14];
    const float* proj_b  = (const float*)d_in[15];
    const float* emb     = (const float*)d_in[16];
    const float* qkv_w   = (const float*)d_in[17];
    const float* qkv_b   = (const float*)d_in[18];
    const float* out_w   = (const float*)d_in[19];
    const float* out_b   = (const float*)d_in[20];
    const float* ln1_g   = (const float*)d_in[21];
    const float* ln1_b   = (const float*)d_in[22];
    const float* ff1_w   = (const float*)d_in[23];
    const float* ff1_b   = (const float*)d_in[24];
    const float* ff2_w   = (const float*)d_in[25];
    const float* ff2_b   = (const float*)d_in[26];
    const float* ln2_g   = (const float*)d_in[27];
    const float* ln2_b   = (const float*)d_in[28];
    const float* heads_w = (const float*)d_in[29];
    const float* heads_b = (const float*)d_in[30];

    const int CONV_SMEM   = 157440;                        /* bytes */
    const int GEMM_SMEM   = (128*40 + 128*65)*4;           /* 53760 B  */
    const int GLN_SMEM128 = (128*40 + 128*65 + 32*132)*4;  /* 70656 B  */
    const int GLN_SMEM256 = (256*40 + 256*65 + 32*132)*4;  /* 124416 B */
    const int ATTN_SMEM   = (3*122*17 + 4*128)*4;          /* 26936 B  */

    cudaFuncSetAttribute(conv_kernel,    cudaFuncAttributeMaxDynamicSharedMemorySize, CONV_SMEM);
    cudaFuncSetAttribute(gemm_kernel,    cudaFuncAttributeMaxDynamicSharedMemorySize, GEMM_SMEM);
    cudaFuncSetAttribute(gemm_ln_kernel, cudaFuncAttributeMaxDynamicSharedMemorySize, GLN_SMEM256);

    float* tokp = nullptr; float* qkvp = nullptr; float* ctxp = nullptr; float* ffp = nullptr;
    cudaGetSymbolAddress((void**)&tokp, g_tok);
    cudaGetSymbolAddress((void**)&qkvp, g_qkv);
    cudaGetSymbolAddress((void**)&ctxp, g_ctx);
    cudaGetSymbolAddress((void**)&ffp,  g_ff);

    conv_kernel<<<BC, 512, CONV_SMEM>>>(
        x, conv1_w, conv1_b, bn1_g, bn1_b, bn1_m, bn1_v,
        conv2_w, conv2_b, bn2_g, bn2_b, bn2_m, bn2_v,
        proj_w, proj_b, emb, tokp);

    for (int l = 0; l < Lln; l++) {
        gemm_kernel<<<dim3(244, 6), 256, GEMM_SMEM>>>(
            tokp, qkv_w + l*3*Dn*Dn, qkv_b + l*3*Dn, qkvp, Dn, 3*Dn, 0);
        attn_kernel<<<Bn*Hn, 128, ATTN_SMEM>>>(qkvp, ctxp);
        gemm_ln_kernel<<<244, 256, GLN_SMEM128>>>(
            ctxp, out_w + l*Dn*Dn, out_b + l*Dn,
            tokp, ln1_g + l*Dn, ln1_b + l*Dn, tokp, Dn);
        gemm_kernel<<<dim3(244, 4), 256, GEMM_SMEM>>>(
            tokp, ff1_w + l*FFn*Dn, ff1_b + l*FFn, ffp, Dn, FFn, 1);
        gemm_ln_kernel<<<244, 256, GLN_SMEM256>>>(
            ffp, ff2_w + l*Dn*FFn, ff2_b + l*Dn,
            tokp, ln2_g + l*Dn, ln2_b + l*Dn, tokp, FFn);
    }

    head_kernel<<<Bn, 128>>>(tokp, sid, heads_w, heads_b, (float*)d_out);
}

// round 8
// speedup vs baseline: 2.3321x; 1.1128x over previous
#include <cuda_runtime.h>
#include <cuda_fp16.h>

#define Bn   64
#define Cn   122
#define Tn   500
#define COn  64
#define Dn   128
#define Hn   8
#define FFn  256
#define Lln  2
#define BC   (Bn*Cn)        /* 7808 = 244*32 */
#define EPSf 1e-5f

typedef unsigned long long ull;
typedef unsigned int uint32;

/* ---------------- scratch (device globals; no allocation) ---------------- */
__device__ float g_tok[BC*Dn];
__device__ float g_qkv[BC*3*Dn];
__device__ float g_ctx[BC*Dn];
__device__ float g_ff [BC*FFn];

/* fast erf-GELU: Abramowitz-Stegun 7.1.26, |erf err| <= 1.5e-7 */
__device__ __forceinline__ float gelu_f(float x){
    float z  = fabsf(x) * 0.70710678118654752440f;
    float t  = __fdividef(1.0f, 1.0f + 0.3275911f*z);
    float poly = t*(0.254829592f + t*(-0.284496736f +
                 t*(1.421413741f + t*(-1.453152027f + t*1.061405429f))));
    float erfz = 1.0f - poly*__expf(-z*z);
    float s = copysignf(erfz, x);
    return 0.5f*x*(1.0f + s);
}

/* packed f32x2 helpers (transformer GEMMs) */
__device__ __forceinline__ ull pk(float a, float b){
    ull r; asm("mov.b64 %0, {%1, %2};" : "=l"(r) : "f"(a), "f"(b)); return r;
}
__device__ __forceinline__ void fma2(ull& d, ull a, ull b){
    asm("fma.rn.f32x2 %0, %1, %2, %0;" : "+l"(d) : "l"(a), "l"(b));
}
__device__ __forceinline__ float2 upk(ull a){
    float2 f; asm("mov.b64 {%0, %1}, %2;" : "=f"(f.x), "=f"(f.y) : "l"(a)); return f;
}

/* fp16 mma m16n8k16, fp32 accum */
__device__ __forceinline__ void mma_f16(float* c,
    uint32 a0, uint32 a1, uint32 a2, uint32 a3, uint32 b0, uint32 b1){
    asm volatile("mma.sync.aligned.m16n8k16.row.col.f32.f16.f16.f32 "
        "{%0,%1,%2,%3}, {%4,%5,%6,%7}, {%8,%9}, {%0,%1,%2,%3};"
        : "+f"(c[0]), "+f"(c[1]), "+f"(c[2]), "+f"(c[3])
        : "r"(a0), "r"(a1), "r"(a2), "r"(a3), "r"(b0), "r"(b1));
}

__device__ __forceinline__ uint32 h2pack(__half lo, __half hi){
    __half2 h = __halves2half2(lo, hi);
    return *(uint32*)&h;
}

/* ============================================================
   Kernel 1: per-(b,c) fused conv pipeline, 256 threads,
   __launch_bounds__(256,2) -> 2 CTAs/SM so the fma/MUFU phases
   of one CTA overlap the tensor (mma) phase of the other.
   conv2 on fp16 tensor cores (m16n8k16), 3-term split:
     D = Wh*ah + Wh*al + Wl*ah
   Weight SMEM buffer time-multiplexed: phase0 sx/sw1 -> wH -> wL.
   SMEM (bytes), total 111104:
     actH @0       uint32[32*264] 33792
     actL @33792   uint32[32*264] 33792
     wbuf @67584   uint32[64*164] 41984   (sx@67584, sw1@69632 in phase0)
     sA1/B1/A2/B2 @109568 float[256]
     spart @110592 float[64]
     sh2   @110848 float[64]
   ============================================================ */
__global__ void __launch_bounds__(256, 2) conv_kernel(
    const float* __restrict__ x,
    const float* __restrict__ w1, const float* __restrict__ cb1,
    const float* __restrict__ g1, const float* __restrict__ be1,
    const float* __restrict__ m1, const float* __restrict__ v1,
    const float* __restrict__ w2, const float* __restrict__ cb2,
    const float* __restrict__ g2, const float* __restrict__ be2,
    const float* __restrict__ m2, const float* __restrict__ v2,
    const float* __restrict__ pw, const float* __restrict__ pb,
    const float* __restrict__ emb, float* __restrict__ tok)
{
    extern __shared__ char smraw[];
    uint32* actH = (uint32*)(smraw);
    uint32* actL = (uint32*)(smraw + 33792);
    uint32* wbuf = (uint32*)(smraw + 67584);
    float* sx    = (float*)(smraw + 67584);   /* aliases wbuf (phase0 only) */
    float* sw1   = (float*)(smraw + 69632);   /* aliases wbuf (phase0 only) */
    float* sA1   = (float*)(smraw + 109568);
    float* sB1   = sA1 + 64;
    float* sA2   = sA1 + 128;
    float* sB2   = sA1 + 192;
    float* spart = (float*)(smraw + 110592);
    float* sh2   = (float*)(smraw + 110848);

    const int bc  = blockIdx.x;
    const int tid = threadIdx.x;

    /* ---- phase 0: input, conv1 weights, BN consts, zero padding ---- */
    for (int i = tid; i < 512; i += 256) {
        int t = i - 4;
        sx[i] = (t >= 0 && t < Tn) ? x[bc*Tn + t] : 0.f;
    }
    for (int i = tid; i < COn*9; i += 256) sw1[i] = w1[i];
    if (tid < 64) {
        float a1 = g1[tid]*rsqrtf(v1[tid]+EPSf);
        sA1[tid] = a1;  sB1[tid] = (cb1[tid]-m1[tid])*a1 + be1[tid];
        float a2 = g2[tid]*rsqrtf(v2[tid]+EPSf);
        sA2[tid] = a2;  sB2[tid] = (cb2[tid]-m2[tid])*a2 + be2[tid];
        spart[tid] = 0.f;
    }
    /* zero pad cols {0,1} U [252,264) in both act arrays */
    for (int i = tid; i < 32*14; i += 256) {
        int row = i / 14, j = i - row*14;
        int col = (j < 2) ? j : (250 + j);
        actH[row*264 + col] = 0u;
        actL[row*264 + col] = 0u;
    }
    __syncthreads();

    /* ---- conv1 + BN + GELU + maxpool(2) -> actH/actL (fp16 split) ---- */
    for (int i = tid; i < COn*250; i += 256) {
        int co = i / 250; int tp = i - co*250;
        const float* wp = &sw1[co*9];
        const float* xp = &sx[2*tp];
        float a0 = 0.f, a1 = 0.f;
        #pragma unroll
        for (int k = 0; k < 9; k++) { a0 += xp[k]*wp[k]; a1 += xp[k+1]*wp[k]; }
        float A = sA1[co], Bv = sB1[co];
        float y0 = gelu_f(a0*A + Bv);
        float y1 = gelu_f(a1*A + Bv);
        float m  = fmaxf(y0, y1);
        __half mh = __float2half_rn(m);
        __half ml = __float2half_rn(m - __half2float(mh));
        int hidx = ((co >> 1)*264 + 2 + tp)*2 + (co & 1);
        ((__half*)actH)[hidx] = mh;
        ((__half*)actL)[hidx] = ml;
    }
    __syncthreads();

    /* ---- load HI weights into wbuf (overwrites sx/sw1) ----
       pair (k=2q, k=2q+1) = (ci, ci+1) same kk */
    for (int i = tid; i < COn*160; i += 256) {
        int co = i / 160, q = i - co*160;
        int k0 = 2*q;
        int kk = k0 >> 6, ci = k0 & 63;
        float wa = w2[co*320 + ci*5 + kk];
        float wb = w2[co*320 + (ci+1)*5 + kk];
        wbuf[co*164 + q] = h2pack(__float2half_rn(wa), __float2half_rn(wb));
    }
    __syncthreads();

    /* ---- conv2 via fp16 tensor cores ----
       8 warps: mchunk = w&1 (32 co), tchunk = w>>1 (64 t). */
    {
        const int wid = tid >> 5, lane = tid & 31;
        const int mchunk = wid & 1, tchunk = wid >> 1;
        const int g = lane >> 2, t4 = lane & 3;

        float acc[2][8][4];
        #pragma unroll
        for (int mi = 0; mi < 2; mi++)
            #pragma unroll
            for (int nj = 0; nj < 8; nj++)
                #pragma unroll
                for (int r = 0; r < 4; r++) acc[mi][nj][r] = 0.f;

        const int mrow0 = mchunk*32 + g;
        const int nbase = tchunk*64 + g;

        /* ---- phase 1: Wh*ah + Wh*al ---- */
        #pragma unroll 4
        for (int c16 = 0; c16 < 20; c16++) {
            const int kk = c16 >> 2;
            const int rb = ((c16 & 3)*8 + t4)*264;
            const int q0 = c16*8 + t4;
            uint32 aH[2][4];
            #pragma unroll
            for (int mi = 0; mi < 2; mi++) {
                int r0 = (mrow0 + mi*16)*164 + q0;
                int r1 = r0 + 8*164;
                aH[mi][0] = wbuf[r0];     aH[mi][1] = wbuf[r1];
                aH[mi][2] = wbuf[r0 + 4]; aH[mi][3] = wbuf[r1 + 4];
            }
            #pragma unroll
            for (int nj = 0; nj < 8; nj++) {
                int cb = rb + nbase + nj*8 + kk;
                uint32 bh0 = actH[cb], bh1 = actH[cb + 4*264];
                uint32 bl0 = actL[cb], bl1 = actL[cb + 4*264];
                #pragma unroll
                for (int mi = 0; mi < 2; mi++) {
                    mma_f16(acc[mi][nj], aH[mi][0], aH[mi][1], aH[mi][2], aH[mi][3], bh0, bh1);
                    mma_f16(acc[mi][nj], aH[mi][0], aH[mi][1], aH[mi][2], aH[mi][3], bl0, bl1);
                }
            }
        }
        __syncthreads();
        /* reload wbuf with LO weights */
        for (int i = tid; i < COn*160; i += 256) {
            int co = i / 160, q = i - co*160;
            int k0 = 2*q;
            int kk = k0 >> 6, ci = k0 & 63;
            float wa = w2[co*320 + ci*5 + kk];
            float wb = w2[co*320 + (ci+1)*5 + kk];
            __half wah = __float2half_rn(wa);
            __half wbh = __float2half_rn(wb);
            __half wal = __float2half_rn(wa - __half2float(wah));
            __half wbl = __float2half_rn(wb - __half2float(wbh));
            wbuf[co*164 + q] = h2pack(wal, wbl);
        }
        __syncthreads();

        /* ---- phase 2: Wl*ah ---- */
        #pragma unroll 4
        for (int c16 = 0; c16 < 20; c16++) {
            const int kk = c16 >> 2;
            const int rb = ((c16 & 3)*8 + t4)*264;
            const int q0 = c16*8 + t4;
            uint32 aL[2][4];
            #pragma unroll
            for (int mi = 0; mi < 2; mi++) {
                int r0 = (mrow0 + mi*16)*164 + q0;
                int r1 = r0 + 8*164;
                aL[mi][0] = wbuf[r0];     aL[mi][1] = wbuf[r1];
                aL[mi][2] = wbuf[r0 + 4]; aL[mi][3] = wbuf[r1 + 4];
            }
            #pragma unroll
            for (int nj = 0; nj < 8; nj++) {
                int cb = rb + nbase + nj*8 + kk;
                uint32 bh0 = actH[cb], bh1 = actH[cb + 4*264];
                #pragma unroll
                for (int mi = 0; mi < 2; mi++)
                    mma_f16(acc[mi][nj], aL[mi][0], aL[mi][1], aL[mi][2], aL[mi][3], bh0, bh1);
            }
        }

        /* epilogue: BN + GELU + partial mean over t */
        #pragma unroll
        for (int mi = 0; mi < 2; mi++) {
            #pragma unroll
            for (int h = 0; h < 2; h++) {
                int r = mchunk*32 + mi*16 + g + h*8;
                float A = sA2[r], Bv = sB2[r];
                float rs = 0.f;
                #pragma unroll
                for (int nj = 0; nj < 8; nj++) {
                    #pragma unroll
                    for (int p = 0; p < 2; p++) {
                        int col = tchunk*64 + nj*8 + 2*t4 + p;
                        if (col < 250)
                            rs += gelu_f(acc[mi][nj][h*2+p]*A + Bv);
                    }
                }
                rs += __shfl_xor_sync(0xffffffffu, rs, 1);
                rs += __shfl_xor_sync(0xffffffffu, rs, 2);
                if (t4 == 0) atomicAdd(&spart[r], rs);
            }
        }
    }
    __syncthreads();
    if (tid < 64) sh2[tid] = spart[tid] * (1.f/250.f);
    __syncthreads();

    /* proj + elec_emb -> tok */
    if (tid < 128) {
        const int d = tid;
        float acc = pb[d];
        const float* pwr = &pw[d*COn];
        #pragma unroll 8
        for (int c = 0; c < 64; c++) acc += sh2[c]*__ldg(&pwr[c]);
        int cidx = bc % Cn;
        tok[bc*Dn + d] = acc + emb[cidx*Dn + d];
    }
}

/* ============================================================
   Kernel 2: tiled GEMM  Y[M,N] = act(X[M,K] @ W[N,K]^T + bias)
   ============================================================ */
__global__ __launch_bounds__(256) void gemm_kernel(
    const float* __restrict__ X, const float* __restrict__ W,
    const float* __restrict__ bias, float* __restrict__ Y,
    int K, int N, int actGelu)
{
    extern __shared__ float sm[];
    float* sxT = sm;            /* [K][40] */
    float* swt = sm + K*40;     /* [K][65] */
    const int row0 = blockIdx.x*32;
    const int e0   = blockIdx.y*64;
    const int tid  = threadIdx.x;

    for (int li = tid; li < 32*K; li += 256) {
        int r = li / K, d = li - r*K;
        sxT[d*40 + r] = X[(row0+r)*K + d];
    }
    for (int li = tid; li < 64*K; li += 256) {
        int e = li / K, d = li - e*K;
        swt[d*65 + e] = W[(e0+e)*K + d];
    }
    __syncthreads();

    const int e_local = tid & 63, tg = tid >> 6;
    float bb = bias[e0 + e_local];
    ull acc[4];
    #pragma unroll
    for (int j = 0; j < 4; j++) acc[j] = pk(bb, bb);
    #pragma unroll 4
    for (int d = 0; d < K; d++) {
        ull Wp = pk(swt[d*65 + e_local], swt[d*65 + e_local]);
        const ull* tp = (const ull*)&sxT[d*40 + tg*8];
        fma2(acc[0], Wp, tp[0]);
        fma2(acc[1], Wp, tp[1]);
        fma2(acc[2], Wp, tp[2]);
        fma2(acc[3], Wp, tp[3]);
    }
    #pragma unroll
    for (int j = 0; j < 4; j++) {
        float2 y = upk(acc[j]);
        if (actGelu) { y.x = gelu_f(y.x); y.y = gelu_f(y.y); }
        Y[(row0 + tg*8 + 2*j  )*N + e0 + e_local] = y.x;
        Y[(row0 + tg*8 + 2*j+1)*N + e0 + e_local] = y.y;
    }
}

/* ============================================================
   Kernel 3: GEMM (N=128) + residual + LayerNorm epilogue
   ============================================================ */
__global__ __launch_bounds__(256) void gemm_ln_kernel(
    const float* __restrict__ X, const float* __restrict__ W,
    const float* __restrict__ bias,
    const float* __restrict__ Res,
    const float* __restrict__ lng, const float* __restrict__ lnb,
    float* __restrict__ Out, int K)
{
    extern __shared__ float sm[];
    float* sxT = sm;               /* [K][40]  */
    float* swt = sm + K*40;        /* [K][65]  */
    float* sy  = swt + K*65;       /* [32][132] */
    const int row0 = blockIdx.x*32;
    const int tid  = threadIdx.x;

    for (int li = tid; li < 32*K; li += 256) {
        int r = li / K, d = li - r*K;
        sxT[d*40 + r] = X[(row0+r)*K + d];
    }
    const int e_local = tid & 63, tg = tid >> 6;

    for (int e0 = 0; e0 < 128; e0 += 64) {
        __syncthreads();
        for (int li = tid; li < 64*K; li += 256) {
            int e = li / K, d = li - e*K;
            swt[d*65 + e] = W[(e0+e)*K + d];
        }
        __syncthreads();
        float bb = bias[e0 + e_local];
        ull acc[4];
        #pragma unroll
        for (int j = 0; j < 4; j++) acc[j] = pk(bb, bb);
        #pragma unroll 4
        for (int d = 0; d < K; d++) {
            ull Wp = pk(swt[d*65 + e_local], swt[d*65 + e_local]);
            const ull* tp = (const ull*)&sxT[d*40 + tg*8];
            fma2(acc[0], Wp, tp[0]);
            fma2(acc[1], Wp, tp[1]);
            fma2(acc[2], Wp, tp[2]);
            fma2(acc[3], Wp, tp[3]);
        }
        #pragma unroll
        for (int j = 0; j < 4; j++) {
            float2 y = upk(acc[j]);
            sy[(tg*8 + 2*j  )*132 + e0 + e_local] = y.x;
            sy[(tg*8 + 2*j+1)*132 + e0 + e_local] = y.y;
        }
    }
    __syncthreads();

    const int w = tid >> 5, lane = tid & 31;
    for (int q = 0; q < 4; q++) {
        int r = w*4 + q;
        float z[4]; float s1 = 0.f, s2 = 0.f;
        #pragma unroll
        for (int i = 0; i < 4; i++) {
            int idx = lane + 32*i;
            float zz = sy[r*132 + idx] + Res[(row0+r)*128 + idx];
            z[i] = zz; s1 += zz; s2 += zz*zz;
        }
        #pragma unroll
        for (int o = 16; o > 0; o >>= 1) {
            s1 += __shfl_xor_sync(0xffffffffu, s1, o);
            s2 += __shfl_xor_sync(0xffffffffu, s2, o);
        }
        float mean = s1*(1.f/128.f);
        float var  = s2*(1.f/128.f) - mean*mean;
        float rs   = rsqrtf(var + EPSf);
        #pragma unroll
        for (int i = 0; i < 4; i++) {
            int idx = lane + 32*i;
            Out[(row0+r)*128 + idx] = (z[i]-mean)*rs*lng[idx] + lnb[idx];
        }
    }
}

/* ============================================================
   Kernel 4: attention per (b, head). seq=122, dh=16.
   ============================================================ */
__global__ __launch_bounds__(128) void attn_kernel(
    const float* __restrict__ qkv, float* __restrict__ ctx)
{
    const int b = blockIdx.x >> 3, h = blockIdx.x & 7;
    extern __shared__ float sm[];
    float* sq = sm;                 /* [122][17] */
    float* sk = sm + 122*17;
    float* sv = sm + 2*122*17;
    float* sattb = sm + 3*122*17;   /* [4][128] */
    const int tid = threadIdx.x;

    for (int li = tid; li < 122*16; li += 128) {
        int s = li >> 4, d = li & 15;
        int base = (b*Cn + s)*384 + h*16 + d;
        sq[s*17 + d] = qkv[base];
        sk[s*17 + d] = qkv[base + 128];
        sv[s*17 + d] = qkv[base + 256];
    }
    __syncthreads();

    const int w = tid >> 5, lane = tid & 31;
    float* satt = sattb + w*128;

    for (int i = w; i < Cn; i += 4) {
        float sc[4];
        #pragma unroll
        for (int c = 0; c < 4; c++) {
            int kk = lane + 32*c;
            if (kk < Cn) {
                float s = 0.f;
                #pragma unroll
                for (int d = 0; d < 16; d++) s += sq[i*17 + d]*sk[kk*17 + d];
                sc[c] = s*0.25f;
            } else sc[c] = -1e30f;
        }
        float mx = fmaxf(fmaxf(sc[0], sc[1]), fmaxf(sc[2], sc[3]));
        #pragma unroll
        for (int o = 16; o > 0; o >>= 1) mx = fmaxf(mx, __shfl_xor_sync(0xffffffffu, mx, o));
        float p[4]; float sum = 0.f;
        #pragma unroll
        for (int c = 0; c < 4; c++) {
            int kk = lane + 32*c;
            p[c] = (kk < Cn) ? expf(sc[c]-mx) : 0.f;
            sum += p[c];
        }
        #pragma unroll
        for (int o = 16; o > 0; o >>= 1) sum += __shfl_xor_sync(0xffffffffu, sum, o);
        float inv = 1.f/sum;
        #pragma unroll
        for (int c = 0; c < 4; c++) {
            int kk = lane + 32*c;
            if (kk < Cn) satt[kk] = p[c]*inv;
        }
        __syncwarp();
        int d = lane & 15, half = lane >> 4;
        float a = 0.f;
        int j0 = half*61;
        for (int j = j0; j < j0 + 61; j++) a += satt[j]*sv[j*17 + d];
        a += __shfl_xor_sync(0xffffffffu, a, 16);
        if (lane < 16) ctx[(b*Cn + i)*Dn + h*16 + d] = a;
        __syncwarp();
    }
}

/* ============================================================
   Kernel 5: mean over C + per-subject head -> out[64,4]
   ============================================================ */
__global__ __launch_bounds__(128) void head_kernel(
    const float* __restrict__ tok, const int* __restrict__ sid,
    const float* __restrict__ hw, const float* __restrict__ hb,
    float* __restrict__ out)
{
    const int b = blockIdx.x;
    __shared__ float sp[128];
    const int d = threadIdx.x;
    float s = 0.f;
    for (int c = 0; c < Cn; c++) s += tok[(b*Cn + c)*Dn + d];
    sp[d] = s*(1.f/(float)Cn);
    __syncthreads();
    const int cls = threadIdx.x >> 5, lane = threadIdx.x & 31;
    const int sb = sid[b];
    float a = 0.f;
    #pragma unroll
    for (int i = 0; i < 4; i++) {
        int dd = lane + 32*i;
        a += sp[dd]*hw[(sb*4 + cls)*Dn + dd];
    }
    #pragma unroll
    for (int o = 16; o > 0; o >>= 1) a += __shfl_xor_sync(0xffffffffu, a, o);
    if (lane == 0) out[b*4 + cls] = a + hb[sb*4 + cls];
}

/* ============================================================ */
extern "C" void kernel_launch(void* const* d_in, const int* in_sizes, int n_in,
                              void* d_out, int out_size)
{
    const float* x       = (const float*)d_in[0];
    const int*   sid     = (const int*  )d_in[1];
    const float* conv1_w = (const float*)d_in[2];
    const float* conv1_b = (const float*)d_in[3];
    const float* bn1_g   = (const float*)d_in[4];
    const float* bn1_b   = (const float*)d_in[5];
    const float* bn1_m   = (const float*)d_in[6];
    const float* bn1_v   = (const float*)d_in[7];
    const float* conv2_w = (const float*)d_in[8];
    const float* conv2_b = (const float*)d_in[9];
    const float* bn2_g   = (const float*)d_in[10];
    const float* bn2_b   = (const float*)d_in[11];
    const float* bn2_m   = (const float*)d_in[12];
    const float* bn2_v   = (const float*)d_in[13];
    const float* proj_w  = (const float*)d_in[14];
    const float* proj_b  = (const float*)d_in[15];
    const float* emb     = (const float*)d_in[16];
    const float* qkv_w   = (const float*)d_in[17];
    const float* qkv_b   = (const float*)d_in[18];
    const float* out_w   = (const float*)d_in[19];
    const float* out_b   = (const float*)d_in[20];
    const float* ln1_g   = (const float*)d_in[21];
    const float* ln1_b   = (const float*)d_in[22];
    const float* ff1_w   = (const float*)d_in[23];
    const float* ff1_b   = (const float*)d_in[24];
    const float* ff2_w   = (const float*)d_in[25];
    const float* ff2_b   = (const float*)d_in[26];
    const float* ln2_g   = (const float*)d_in[27];
    const float* ln2_b   = (const float*)d_in[28];
    const float* heads_w = (const float*)d_in[29];
    const float* heads_b = (const float*)d_in[30];

    const int CONV_SMEM   = 111104;                        /* bytes */
    const int GEMM_SMEM   = (128*40 + 128*65)*4;           /* 53760 B  */
    const int GLN_SMEM128 = (128*40 + 128*65 + 32*132)*4;  /* 70656 B  */
    const int GLN_SMEM256 = (256*40 + 256*65 + 32*132)*4;  /* 124416 B */
    const int ATTN_SMEM   = (3*122*17 + 4*128)*4;          /* 26936 B  */

    cudaFuncSetAttribute(conv_kernel,    cudaFuncAttributeMaxDynamicSharedMemorySize, CONV_SMEM);
    cudaFuncSetAttribute(gemm_kernel,    cudaFuncAttributeMaxDynamicSharedMemorySize, GEMM_SMEM);
    cudaFuncSetAttribute(gemm_ln_kernel, cudaFuncAttributeMaxDynamicSharedMemorySize, GLN_SMEM256);

    float* tokp = nullptr; float* qkvp = nullptr; float* ctxp = nullptr; float* ffp = nullptr;
    cudaGetSymbolAddress((void**)&tokp, g_tok);
    cudaGetSymbolAddress((void**)&qkvp, g_qkv);
    cudaGetSymbolAddress((void**)&ctxp, g_ctx);
    cudaGetSymbolAddress((void**)&ffp,  g_ff);

    conv_kernel<<<BC, 256, CONV_SMEM>>>(
        x, conv1_w, conv1_b, bn1_g, bn1_b, bn1_m, bn1_v,
        conv2_w, conv2_b, bn2_g, bn2_b, bn2_m, bn2_v,
        proj_w, proj_b, emb, tokp);

    for (int l = 0; l < Lln; l++) {
        gemm_kernel<<<dim3(244, 6), 256, GEMM_SMEM>>>(
            tokp, qkv_w + l*3*Dn*Dn, qkv_b + l*3*Dn, qkvp, Dn, 3*Dn, 0);
        attn_kernel<<<Bn*Hn, 128, ATTN_SMEM>>>(qkvp, ctxp);
        gemm_ln_kernel<<<244, 256, GLN_SMEM128>>>(
            ctxp, out_w + l*Dn*Dn, out_b + l*Dn,
            tokp, ln1_g + l*Dn, ln1_b + l*Dn, tokp, Dn);
        gemm_kernel<<<dim3(244, 4), 256, GEMM_SMEM>>>(
            tokp, ff1_w + l*FFn*Dn, ff1_b + l*FFn, ffp, Dn, FFn, 1);
        gemm_ln_kernel<<<244, 256, GLN_SMEM256>>>(
            ffp, ff2_w + l*Dn*FFn, ff2_b + l*Dn,
            tokp, ln2_g + l*Dn, ln2_b + l*Dn, tokp, FFn);
    }

    head_kernel<<<Bn, 128>>>(tokp, sid, heads_w, heads_b, (float*)d_out);
}

// round 9
// speedup vs baseline: 2.3958x; 1.0273x over previous
#include <cuda_runtime.h>
#include <cuda_fp16.h>

#define Bn   64
#define Cn   122
#define Tn   500
#define COn  64
#define Dn   128
#define Hn   8
#define FFn  256
#define Lln  2
#define BC   (Bn*Cn)        /* 7808 = 3904*2 */
#define EPSf 1e-5f

typedef unsigned long long ull;
typedef unsigned int uint32;

/* ---------------- scratch (device globals; no allocation) ---------------- */
__device__ float g_tok[BC*Dn];
__device__ float g_qkv[BC*3*Dn];
__device__ float g_ctx[BC*Dn];
__device__ float g_ff [BC*FFn];

/* fast erf-GELU: Abramowitz-Stegun 7.1.26, |erf err| <= 1.5e-7 */
__device__ __forceinline__ float gelu_f(float x){
    float z  = fabsf(x) * 0.70710678118654752440f;
    float t  = __fdividef(1.0f, 1.0f + 0.3275911f*z);
    float poly = t*(0.254829592f + t*(-0.284496736f +
                 t*(1.421413741f + t*(-1.453152027f + t*1.061405429f))));
    float erfz = 1.0f - poly*__expf(-z*z);
    float s = copysignf(erfz, x);
    return 0.5f*x*(1.0f + s);
}

/* packed f32x2 helpers (transformer GEMMs) */
__device__ __forceinline__ ull pk(float a, float b){
    ull r; asm("mov.b64 %0, {%1, %2};" : "=l"(r) : "f"(a), "f"(b)); return r;
}
__device__ __forceinline__ void fma2(ull& d, ull a, ull b){
    asm("fma.rn.f32x2 %0, %1, %2, %0;" : "+l"(d) : "l"(a), "l"(b));
}
__device__ __forceinline__ float2 upk(ull a){
    float2 f; asm("mov.b64 {%0, %1}, %2;" : "=f"(f.x), "=f"(f.y) : "l"(a)); return f;
}

/* fp16 mma m16n8k16, fp32 accum */
__device__ __forceinline__ void mma_f16(float* c,
    uint32 a0, uint32 a1, uint32 a2, uint32 a3, uint32 b0, uint32 b1){
    asm volatile("mma.sync.aligned.m16n8k16.row.col.f32.f16.f16.f32 "
        "{%0,%1,%2,%3}, {%4,%5,%6,%7}, {%8,%9}, {%0,%1,%2,%3};"
        : "+f"(c[0]), "+f"(c[1]), "+f"(c[2]), "+f"(c[3])
        : "r"(a0), "r"(a1), "r"(a2), "r"(a3), "r"(b0), "r"(b1));
}

__device__ __forceinline__ uint32 h2pack(__half lo, __half hi){
    __half2 h = __halves2half2(lo, hi);
    return *(uint32*)&h;
}

/* conv1 + BN + GELU + maxpool(2) -> actH/actL (fp16 split) */
__device__ __forceinline__ void conv1_run(
    int i0, int stride, const float* __restrict__ sx,
    const float* __restrict__ sw1,
    const float* __restrict__ sA1, const float* __restrict__ sB1,
    uint32* __restrict__ actH, uint32* __restrict__ actL)
{
    for (int i = i0; i < COn*250; i += stride) {
        int co = i / 250; int tp = i - co*250;
        const float* wp = &sw1[co*9];
        const float* xp = &sx[2*tp];
        float a0 = 0.f, a1 = 0.f;
        #pragma unroll
        for (int k = 0; k < 9; k++) { a0 += xp[k]*wp[k]; a1 += xp[k+1]*wp[k]; }
        float A = sA1[co], Bv = sB1[co];
        float y0 = gelu_f(a0*A + Bv);
        float y1 = gelu_f(a1*A + Bv);
        float m  = fmaxf(y0, y1);
        __half mh = __float2half_rn(m);
        __half ml = __float2half_rn(m - __half2float(mh));
        int hidx = ((co >> 1)*264 + 2 + tp)*2 + (co & 1);
        ((__half*)actH)[hidx] = mh;
        ((__half*)actL)[hidx] = ml;
    }
}

/* conv2 mma (3-term fp16) + BN/GELU/mean epilogue + proj, run by warps 0-7
   (256 threads). Internal sync via named barrier 1 (256 threads). */
__device__ __forceinline__ void mma_sample(
    const uint32* __restrict__ actH, const uint32* __restrict__ actL,
    const uint32* __restrict__ wH,   const uint32* __restrict__ wL,
    const float* __restrict__ sA2,   const float* __restrict__ sB2,
    float* __restrict__ spart, float* __restrict__ sh2,
    const float* __restrict__ pw, const float* __restrict__ pb,
    const float* __restrict__ emb, float* __restrict__ tok,
    int bc, int tid)
{
    const int wid = tid >> 5, lane = tid & 31;
    const int mchunk = wid & 1, tchunk = wid >> 1;   /* wid 0..7 */
    const int g = lane >> 2, t4 = lane & 3;

    float acc[2][8][4];
    #pragma unroll
    for (int mi = 0; mi < 2; mi++)
        #pragma unroll
        for (int nj = 0; nj < 8; nj++)
            #pragma unroll
            for (int r = 0; r < 4; r++) acc[mi][nj][r] = 0.f;

    const int mrow0 = mchunk*32 + g;
    const int nbase = tchunk*64 + g;

    #pragma unroll 4
    for (int c16 = 0; c16 < 20; c16++) {
        const int kk = c16 >> 2;
        const int rb = ((c16 & 3)*8 + t4)*264;
        const int q0 = c16*8 + t4;
        uint32 aH[2][4], aL[2][4];
        #pragma unroll
        for (int mi = 0; mi < 2; mi++) {
            int r0 = (mrow0 + mi*16)*164 + q0;
            int r1 = r0 + 8*164;
            aH[mi][0] = wH[r0];     aH[mi][1] = wH[r1];
            aH[mi][2] = wH[r0 + 4]; aH[mi][3] = wH[r1 + 4];
            aL[mi][0] = wL[r0];     aL[mi][1] = wL[r1];
            aL[mi][2] = wL[r0 + 4]; aL[mi][3] = wL[r1 + 4];
        }
        #pragma unroll
        for (int nj = 0; nj < 8; nj++) {
            int cb = rb + nbase + nj*8 + kk;
            uint32 bh0 = actH[cb], bh1 = actH[cb + 4*264];
            uint32 bl0 = actL[cb], bl1 = actL[cb + 4*264];
            #pragma unroll
            for (int mi = 0; mi < 2; mi++) {
                mma_f16(acc[mi][nj], aH[mi][0], aH[mi][1], aH[mi][2], aH[mi][3], bh0, bh1);
                mma_f16(acc[mi][nj], aH[mi][0], aH[mi][1], aH[mi][2], aH[mi][3], bl0, bl1);
                mma_f16(acc[mi][nj], aL[mi][0], aL[mi][1], aL[mi][2], aL[mi][3], bh0, bh1);
            }
        }
    }

    /* epilogue: BN + GELU + partial mean over t */
    #pragma unroll
    for (int mi = 0; mi < 2; mi++) {
        #pragma unroll
        for (int h = 0; h < 2; h++) {
            int r = mchunk*32 + mi*16 + g + h*8;
            float A = sA2[r], Bv = sB2[r];
            float rs = 0.f;
            #pragma unroll
            for (int nj = 0; nj < 8; nj++) {
                #pragma unroll
                for (int p = 0; p < 2; p++) {
                    int col = tchunk*64 + nj*8 + 2*t4 + p;
                    if (col < 250)
                        rs += gelu_f(acc[mi][nj][h*2+p]*A + Bv);
                }
            }
            rs += __shfl_xor_sync(0xffffffffu, rs, 1);
            rs += __shfl_xor_sync(0xffffffffu, rs, 2);
            if (t4 == 0) atomicAdd(&spart[r], rs);
        }
    }
    asm volatile("bar.sync 1, 256;" ::: "memory");
    if (tid < 64) sh2[tid] = spart[tid] * (1.f/250.f);
    asm volatile("bar.sync 1, 256;" ::: "memory");

    /* proj + elec_emb -> tok */
    if (tid < 128) {
        const int d = tid;
        float acc2 = pb[d];
        const float* pwr = &pw[d*COn];
        #pragma unroll 8
        for (int c = 0; c < 64; c++) acc2 += sh2[c]*__ldg(&pwr[c]);
        int cidx = bc % Cn;
        tok[bc*Dn + d] = acc2 + emb[cidx*Dn + d];
    }
}

/* ============================================================
   Kernel 1: fused conv pipeline, 512 threads, 2 samples/block,
   warp-specialized pipeline:
     stage A: all warps  : loads + conv1(s0)
     stage B: warps 0-7  : mma(s0)+epi+proj | warps 8-15: conv1(s1)
     stage C: warps 0-7  : mma(s1)+epi+proj
   SMEM (bytes), total 227584:
     act0H @0       act0L @33792   act1H @67584  act1L @101376
     wH @135168 (41984)  wL @177152 (41984)
     sx0 @219136  sx1 @221184  sw1 @223232
     sA1/B1/A2/B2 @225536  spart0 @226560  spart1 @226816
     sh20 @227072  sh21 @227328
   ============================================================ */
__global__ void __launch_bounds__(512, 1) conv_kernel(
    const float* __restrict__ x,
    const float* __restrict__ w1, const float* __restrict__ cb1,
    const float* __restrict__ g1, const float* __restrict__ be1,
    const float* __restrict__ m1, const float* __restrict__ v1,
    const float* __restrict__ w2, const float* __restrict__ cb2,
    const float* __restrict__ g2, const float* __restrict__ be2,
    const float* __restrict__ m2, const float* __restrict__ v2,
    const float* __restrict__ pw, const float* __restrict__ pb,
    const float* __restrict__ emb, float* __restrict__ tok)
{
    extern __shared__ char smraw[];
    uint32* act0H = (uint32*)(smraw);
    uint32* act0L = (uint32*)(smraw + 33792);
    uint32* act1H = (uint32*)(smraw + 67584);
    uint32* act1L = (uint32*)(smraw + 101376);
    uint32* wH    = (uint32*)(smraw + 135168);
    uint32* wL    = (uint32*)(smraw + 177152);
    float* sx0    = (float*)(smraw + 219136);
    float* sx1    = (float*)(smraw + 221184);
    float* sw1    = (float*)(smraw + 223232);
    float* sA1    = (float*)(smraw + 225536);
    float* sB1    = sA1 + 64;
    float* sA2    = sA1 + 128;
    float* sB2    = sA1 + 192;
    float* spart0 = (float*)(smraw + 226560);
    float* spart1 = (float*)(smraw + 226816);
    float* sh20   = (float*)(smraw + 227072);
    float* sh21   = (float*)(smraw + 227328);

    const int bc0 = blockIdx.x*2;
    const int bc1 = bc0 + 1;
    const int tid = threadIdx.x;
    const int wid = tid >> 5;

    /* ---- stage A: all loads + conv1(s0) by all warps ---- */
    {
        int t = tid - 4;
        sx0[tid] = (t >= 0 && t < Tn) ? x[bc0*Tn + t] : 0.f;
        sx1[tid] = (t >= 0 && t < Tn) ? x[bc1*Tn + t] : 0.f;
    }
    for (int i = tid; i < COn*9; i += 512) sw1[i] = w1[i];
    if (tid < 64) {
        float a1 = g1[tid]*rsqrtf(v1[tid]+EPSf);
        sA1[tid] = a1;  sB1[tid] = (cb1[tid]-m1[tid])*a1 + be1[tid];
        float a2 = g2[tid]*rsqrtf(v2[tid]+EPSf);
        sA2[tid] = a2;  sB2[tid] = (cb2[tid]-m2[tid])*a2 + be2[tid];
        spart0[tid] = 0.f;  spart1[tid] = 0.f;
    }
    /* weights hi+lo: pair (k=2q, k=2q+1) = (ci, ci+1), same kk */
    for (int i = tid; i < COn*160; i += 512) {
        int co = i / 160, q = i - co*160;
        int k0 = 2*q;
        int kk = k0 >> 6, ci = k0 & 63;
        float wa = w2[co*320 + ci*5 + kk];
        float wb = w2[co*320 + (ci+1)*5 + kk];
        __half wah = __float2half_rn(wa);
        __half wbh = __float2half_rn(wb);
        wH[co*164 + q] = h2pack(wah, wbh);
        wL[co*164 + q] = h2pack(__float2half_rn(wa - __half2float(wah)),
                                __float2half_rn(wb - __half2float(wbh)));
    }
    /* zero pad cols {0,1} U [252,264) in all act arrays */
    for (int i = tid; i < 32*14; i += 512) {
        int row = i / 14, j = i - row*14;
        int col = (j < 2) ? j : (250 + j);
        act0H[row*264 + col] = 0u;  act0L[row*264 + col] = 0u;
        act1H[row*264 + col] = 0u;  act1L[row*264 + col] = 0u;
    }
    __syncthreads();

    conv1_run(tid, 512, sx0, sw1, sA1, sB1, act0H, act0L);
    __syncthreads();

    /* ---- stage B: mma(s0) || conv1(s1) ---- */
    if (wid < 8) {
        mma_sample(act0H, act0L, wH, wL, sA2, sB2, spart0, sh20,
                   pw, pb, emb, tok, bc0, tid);
    } else {
        conv1_run(tid - 256, 256, sx1, sw1, sA1, sB1, act1H, act1L);
    }
    __syncthreads();

    /* ---- stage C: mma(s1) ---- */
    if (wid < 8) {
        mma_sample(act1H, act1L, wH, wL, sA2, sB2, spart1, sh21,
                   pw, pb, emb, tok, bc1, tid);
    }
}

/* ============================================================
   Kernel 2: tiled GEMM  Y[M,N] = act(X[M,K] @ W[N,K]^T + bias)
   ============================================================ */
__global__ __launch_bounds__(256) void gemm_kernel(
    const float* __restrict__ X, const float* __restrict__ W,
    const float* __restrict__ bias, float* __restrict__ Y,
    int K, int N, int actGelu)
{
    extern __shared__ float sm[];
    float* sxT = sm;            /* [K][40] */
    float* swt = sm + K*40;     /* [K][65] */
    const int row0 = blockIdx.x*32;
    const int e0   = blockIdx.y*64;
    const int tid  = threadIdx.x;

    for (int li = tid; li < 32*K; li += 256) {
        int r = li / K, d = li - r*K;
        sxT[d*40 + r] = X[(row0+r)*K + d];
    }
    for (int li = tid; li < 64*K; li += 256) {
        int e = li / K, d = li - e*K;
        swt[d*65 + e] = W[(e0+e)*K + d];
    }
    __syncthreads();

    const int e_local = tid & 63, tg = tid >> 6;
    float bb = bias[e0 + e_local];
    ull acc[4];
    #pragma unroll
    for (int j = 0; j < 4; j++) acc[j] = pk(bb, bb);
    #pragma unroll 4
    for (int d = 0; d < K; d++) {
        ull Wp = pk(swt[d*65 + e_local], swt[d*65 + e_local]);
        const ull* tp = (const ull*)&sxT[d*40 + tg*8];
        fma2(acc[0], Wp, tp[0]);
        fma2(acc[1], Wp, tp[1]);
        fma2(acc[2], Wp, tp[2]);
        fma2(acc[3], Wp, tp[3]);
    }
    #pragma unroll
    for (int j = 0; j < 4; j++) {
        float2 y = upk(acc[j]);
        if (actGelu) { y.x = gelu_f(y.x); y.y = gelu_f(y.y); }
        Y[(row0 + tg*8 + 2*j  )*N + e0 + e_local] = y.x;
        Y[(row0 + tg*8 + 2*j+1)*N + e0 + e_local] = y.y;
    }
}

/* ============================================================
   Kernel 3: GEMM (N=128) + residual + LayerNorm epilogue
   ============================================================ */
__global__ __launch_bounds__(256) void gemm_ln_kernel(
    const float* __restrict__ X, const float* __restrict__ W,
    const float* __restrict__ bias,
    const float* __restrict__ Res,
    const float* __restrict__ lng, const float* __restrict__ lnb,
    float* __restrict__ Out, int K)
{
    extern __shared__ float sm[];
    float* sxT = sm;               /* [K][40]  */
    float* swt = sm + K*40;        /* [K][65]  */
    float* sy  = swt + K*65;       /* [32][132] */
    const int row0 = blockIdx.x*32;
    const int tid  = threadIdx.x;

    for (int li = tid; li < 32*K; li += 256) {
        int r = li / K, d = li - r*K;
        sxT[d*40 + r] = X[(row0+r)*K + d];
    }
    const int e_local = tid & 63, tg = tid >> 6;

    for (int e0 = 0; e0 < 128; e0 += 64) {
        __syncthreads();
        for (int li = tid; li < 64*K; li += 256) {
            int e = li / K, d = li - e*K;
            swt[d*65 + e] = W[(e0+e)*K + d];
        }
        __syncthreads();
        float bb = bias[e0 + e_local];
        ull acc[4];
        #pragma unroll
        for (int j = 0; j < 4; j++) acc[j] = pk(bb, bb);
        #pragma unroll 4
        for (int d = 0; d < K; d++) {
            ull Wp = pk(swt[d*65 + e_local], swt[d*65 + e_local]);
            const ull* tp = (const ull*)&sxT[d*40 + tg*8];
            fma2(acc[0], Wp, tp[0]);
            fma2(acc[1], Wp, tp[1]);
            fma2(acc[2], Wp, tp[2]);
            fma2(acc[3], Wp, tp[3]);
        }
        #pragma unroll
        for (int j = 0; j < 4; j++) {
            float2 y = upk(acc[j]);
            sy[(tg*8 + 2*j  )*132 + e0 + e_local] = y.x;
            sy[(tg*8 + 2*j+1)*132 + e0 + e_local] = y.y;
        }
    }
    __syncthreads();

    const int w = tid >> 5, lane = tid & 31;
    for (int q = 0; q < 4; q++) {
        int r = w*4 + q;
        float z[4]; float s1 = 0.f, s2 = 0.f;
        #pragma unroll
        for (int i = 0; i < 4; i++) {
            int idx = lane + 32*i;
            float zz = sy[r*132 + idx] + Res[(row0+r)*128 + idx];
            z[i] = zz; s1 += zz; s2 += zz*zz;
        }
        #pragma unroll
        for (int o = 16; o > 0; o >>= 1) {
            s1 += __shfl_xor_sync(0xffffffffu, s1, o);
            s2 += __shfl_xor_sync(0xffffffffu, s2, o);
        }
        float mean = s1*(1.f/128.f);
        float var  = s2*(1.f/128.f) - mean*mean;
        float rs   = rsqrtf(var + EPSf);
        #pragma unroll
        for (int i = 0; i < 4; i++) {
            int idx = lane + 32*i;
            Out[(row0+r)*128 + idx] = (z[i]-mean)*rs*lng[idx] + lnb[idx];
        }
    }
}

/* ============================================================
   Kernel 4: attention per (b, head). seq=122, dh=16.
   ============================================================ */
__global__ __launch_bounds__(128) void attn_kernel(
    const float* __restrict__ qkv, float* __restrict__ ctx)
{
    const int b = blockIdx.x >> 3, h = blockIdx.x & 7;
    extern __shared__ float sm[];
    float* sq = sm;                 /* [122][17] */
    float* sk = sm + 122*17;
    float* sv = sm + 2*122*17;
    float* sattb = sm + 3*122*17;   /* [4][128] */
    const int tid = threadIdx.x;

    for (int li = tid; li < 122*16; li += 128) {
        int s = li >> 4, d = li & 15;
        int base = (b*Cn + s)*384 + h*16 + d;
        sq[s*17 + d] = qkv[base];
        sk[s*17 + d] = qkv[base + 128];
        sv[s*17 + d] = qkv[base + 256];
    }
    __syncthreads();

    const int w = tid >> 5, lane = tid & 31;
    float* satt = sattb + w*128;

    for (int i = w; i < Cn; i += 4) {
        float sc[4];
        #pragma unroll
        for (int c = 0; c < 4; c++) {
            int kk = lane + 32*c;
            if (kk < Cn) {
                float s = 0.f;
                #pragma unroll
                for (int d = 0; d < 16; d++) s += sq[i*17 + d]*sk[kk*17 + d];
                sc[c] = s*0.25f;
            } else sc[c] = -1e30f;
        }
        float mx = fmaxf(fmaxf(sc[0], sc[1]), fmaxf(sc[2], sc[3]));
        #pragma unroll
        for (int o = 16; o > 0; o >>= 1) mx = fmaxf(mx, __shfl_xor_sync(0xffffffffu, mx, o));
        float p[4]; float sum = 0.f;
        #pragma unroll
        for (int c = 0; c < 4; c++) {
            int kk = lane + 32*c;
            p[c] = (kk < Cn) ? __expf(sc[c]-mx) : 0.f;
            sum += p[c];
        }
        #pragma unroll
        for (int o = 16; o > 0; o >>= 1) sum += __shfl_xor_sync(0xffffffffu, sum, o);
        float inv = __fdividef(1.f, sum);
        #pragma unroll
        for (int c = 0; c < 4; c++) {
            int kk = lane + 32*c;
            if (kk < Cn) satt[kk] = p[c]*inv;
        }
        __syncwarp();
        int d = lane & 15, half = lane >> 4;
        float a = 0.f;
        int j0 = half*61;
        for (int j = j0; j < j0 + 61; j++) a += satt[j]*sv[j*17 + d];
        a += __shfl_xor_sync(0xffffffffu, a, 16);
        if (lane < 16) ctx[(b*Cn + i)*Dn + h*16 + d] = a;
        __syncwarp();
    }
}

/* ============================================================
   Kernel 5: mean over C + per-subject head -> out[64,4]
   ============================================================ */
__global__ __launch_bounds__(128) void head_kernel(
    const float* __restrict__ tok, const int* __restrict__ sid,
    const float* __restrict__ hw, const float* __restrict__ hb,
    float* __restrict__ out)
{
    const int b = blockIdx.x;
    __shared__ float sp[128];
    const int d = threadIdx.x;
    float s = 0.f;
    for (int c = 0; c < Cn; c++) s += tok[(b*Cn + c)*Dn + d];
    sp[d] = s*(1.f/(float)Cn);
    __syncthreads();
    const int cls = threadIdx.x >> 5, lane = threadIdx.x & 31;
    const int sb = sid[b];
    float a = 0.f;
    #pragma unroll
    for (int i = 0; i < 4; i++) {
        int dd = lane + 32*i;
        a += sp[dd]*hw[(sb*4 + cls)*Dn + dd];
    }
    #pragma unroll
    for (int o = 16; o > 0; o >>= 1) a += __shfl_xor_sync(0xffffffffu, a, o);
    if (lane == 0) out[b*4 + cls] = a + hb[sb*4 + cls];
}

/* ============================================================ */
extern "C" void kernel_launch(void* const* d_in, const int* in_sizes, int n_in,
                              void* d_out, int out_size)
{
    const float* x       = (const float*)d_in[0];
    const int*   sid     = (const int*  )d_in[1];
    const float* conv1_w = (const float*)d_in[2];
    const float* conv1_b = (const float*)d_in[3];
    const float* bn1_g   = (const float*)d_in[4];
    const float* bn1_b   = (const float*)d_in[5];
    const float* bn1_m   = (const float*)d_in[6];
    const float* bn1_v   = (const float*)d_in[7];
    const float* conv2_w = (const float*)d_in[8];
    const float* conv2_b = (const float*)d_in[9];
    const float* bn2_g   = (const float*)d_in[10];
    const float* bn2_b   = (const float*)d_in[11];
    const float* bn2_m   = (const float*)d_in[12];
    const float* bn2_v   = (const float*)d_in[13];
    const float* proj_w  = (const float*)d_in[14];
    const float* proj_b  = (const float*)d_in[15];
    const float* emb     = (const float*)d_in[16];
    const float* qkv_w   = (const float*)d_in[17];
    const float* qkv_b   = (const float*)d_in[18];
    const float* out_w   = (const float*)d_in[19];
    const float* out_b   = (const float*)d_in[20];
    const float* ln1_g   = (const float*)d_in[21];
    const float* ln1_b   = (const float*)d_in[22];
    const float* ff1_w   = (const float*)d_in[23];
    const float* ff1_b   = (const float*)d_in[24];
    const float* ff2_w   = (const float*)d_in[25];
    const float* ff2_b   = (const float*)d_in[26];
    const float* ln2_g   = (const float*)d_in[27];
    const float* ln2_b   = (const float*)d_in[28];
    const float* heads_w = (const float*)d_in[29];
    const float* heads_b = (const float*)d_in[30];

    const int CONV_SMEM   = 227584;                        /* bytes */
    const int GEMM_SMEM   = (128*40 + 128*65)*4;           /* 53760 B  */
    const int GLN_SMEM128 = (128*40 + 128*65 + 32*132)*4;  /* 70656 B  */
    const int GLN_SMEM256 = (256*40 + 256*65 + 32*132)*4;  /* 124416 B */
    const int ATTN_SMEM   = (3*122*17 + 4*128)*4;          /* 26936 B  */

    cudaFuncSetAttribute(conv_kernel,    cudaFuncAttributeMaxDynamicSharedMemorySize, CONV_SMEM);
    cudaFuncSetAttribute(gemm_kernel,    cudaFuncAttributeMaxDynamicSharedMemorySize, GEMM_SMEM);
    cudaFuncSetAttribute(gemm_ln_kernel, cudaFuncAttributeMaxDynamicSharedMemorySize, GLN_SMEM256);

    float* tokp = nullptr; float* qkvp = nullptr; float* ctxp = nullptr; float* ffp = nullptr;
    cudaGetSymbolAddress((void**)&tokp, g_tok);
    cudaGetSymbolAddress((void**)&qkvp, g_qkv);
    cudaGetSymbolAddress((void**)&ctxp, g_ctx);
    cudaGetSymbolAddress((void**)&ffp,  g_ff);

    conv_kernel<<<BC/2, 512, CONV_SMEM>>>(
        x, conv1_w, conv1_b, bn1_g, bn1_b, bn1_m, bn1_v,
        conv2_w, conv2_b, bn2_g, bn2_b, bn2_m, bn2_v,
        proj_w, proj_b, emb, tokp);

    for (int l = 0; l < Lln; l++) {
        gemm_kernel<<<dim3(244, 6), 256, GEMM_SMEM>>>(
            tokp, qkv_w + l*3*Dn*Dn, qkv_b + l*3*Dn, qkvp, Dn, 3*Dn, 0);
        attn_kernel<<<Bn*Hn, 128, ATTN_SMEM>>>(qkvp, ctxp);
        gemm_ln_kernel<<<244, 256, GLN_SMEM128>>>(
            ctxp, out_w + l*Dn*Dn, out_b + l*Dn,
            tokp, ln1_g + l*Dn, ln1_b + l*Dn, tokp, Dn);
        gemm_kernel<<<dim3(244, 4), 256, GEMM_SMEM>>>(
            tokp, ff1_w + l*FFn*Dn, ff1_b + l*FFn, ffp, Dn, FFn, 1);
        gemm_ln_kernel<<<244, 256, GLN_SMEM256>>>(
            ffp, ff2_w + l*Dn*FFn, ff2_b + l*Dn,
            tokp, ln2_g + l*Dn, ln2_b + l*Dn, tokp, FFn);
    }

    head_kernel<<<Bn, 128>>>(tokp, sid, heads_w, heads_b, (float*)d_out);
}